// round 1
// baseline (speedup 1.0000x reference)
#include <cuda_runtime.h>
#include <math.h>

#define B_   4
#define T_   2048
#define C_   1024
#define H_   16
#define D_   64
#define M_   (B_ * T_)           // 8192 rows
#define LN_EPS 1e-5f

// ---------------- scratch (static device globals; no allocation) -----------
__device__ float g_qkv[(size_t)M_ * 3 * C_];   // 100 MB
__device__ float g_att[(size_t)M_ * C_];       // 33 MB
__device__ float g_x1 [(size_t)M_ * C_];       // 33 MB
__device__ float g_hb [(size_t)M_ * 4 * C_];   // 134 MB
__device__ float g_mlp[(size_t)M_ * C_];       // 33 MB

__device__ __forceinline__ float gelu_exact(float x) {
    return 0.5f * x * (1.0f + erff(x * 0.70710678118654752440f));
}

// ---------------- 128x128x8 fp32 SGEMM, bias (+ optional exact GELU) -------
// A [M,K] row-major, W [K,N] row-major, C [M,N].  M%128==0, N%128==0, K%8==0.
template <bool GELU>
__global__ void __launch_bounds__(256) gemm_bias(
    const float* __restrict__ A, const float* __restrict__ W,
    const float* __restrict__ bias, float* __restrict__ Cmat,
    int M, int N, int K)
{
    __shared__ float As[8][128];
    __shared__ float Bs[8][128];

    const int tid = threadIdx.x;
    const int bc  = blockIdx.x;   // N tile
    const int br  = blockIdx.y;   // M tile
    const int ty  = tid >> 4;     // 0..15  -> rows ty*8..+7
    const int tx  = tid & 15;     // 0..15  -> cols tx*8..+7

    // A-load mapping: 2 threads per row, one float4 each
    const int arow = tid >> 1;          // 0..127
    const int acol = (tid & 1) * 4;     // 0 or 4
    // B-load mapping: 32 threads per k-row, one float4 each
    const int brow = tid >> 5;          // 0..7
    const int bcol = (tid & 31) * 4;    // 0..124

    const float* Aptr = A + (size_t)(br * 128 + arow) * K + acol;
    const float* Bptr = W + (size_t)brow * N + (size_t)bc * 128 + bcol;

    float acc[8][8];
#pragma unroll
    for (int i = 0; i < 8; i++)
#pragma unroll
        for (int j = 0; j < 8; j++) acc[i][j] = 0.f;

    for (int k0 = 0; k0 < K; k0 += 8) {
        float4 av = *(const float4*)(Aptr + k0);
        As[acol + 0][arow] = av.x;
        As[acol + 1][arow] = av.y;
        As[acol + 2][arow] = av.z;
        As[acol + 3][arow] = av.w;
        *(float4*)&Bs[brow][bcol] = *(const float4*)(Bptr + (size_t)k0 * N);
        __syncthreads();

#pragma unroll
        for (int kk = 0; kk < 8; kk++) {
            float a[8], b[8];
            *(float4*)&a[0] = *(const float4*)&As[kk][ty * 8];
            *(float4*)&a[4] = *(const float4*)&As[kk][ty * 8 + 4];
            *(float4*)&b[0] = *(const float4*)&Bs[kk][tx * 8];
            *(float4*)&b[4] = *(const float4*)&Bs[kk][tx * 8 + 4];
#pragma unroll
            for (int i = 0; i < 8; i++)
#pragma unroll
                for (int j = 0; j < 8; j++)
                    acc[i][j] = fmaf(a[i], b[j], acc[i][j]);
        }
        __syncthreads();
    }

    float bv[8];
#pragma unroll
    for (int j = 0; j < 8; j++) bv[j] = bias[bc * 128 + tx * 8 + j];

#pragma unroll
    for (int i = 0; i < 8; i++) {
        const size_t row = (size_t)br * 128 + ty * 8 + i;
        float o[8];
#pragma unroll
        for (int j = 0; j < 8; j++) {
            float v = acc[i][j] + bv[j];
            if (GELU) v = gelu_exact(v);
            o[j] = v;
        }
        float* dst = Cmat + row * N + (size_t)bc * 128 + tx * 8;
        *(float4*)(dst)     = *(float4*)&o[0];
        *(float4*)(dst + 4) = *(float4*)&o[4];
    }
}

// ---------------- causal flash attention: 64 queries x 32-key tiles --------
// qkv [B,T,3C] row-major; q = cols[0,C), k = [C,2C), v = [2C,3C); head h at h*64.
// grid (T/64, H, B), 256 threads. Online softmax, all operands staged in SMEM.
__global__ void __launch_bounds__(256) attn_kernel(
    const float* __restrict__ qkv, float* __restrict__ y)
{
    __shared__ float Qs[64][65];
    __shared__ float Ks[32][65];
    __shared__ float Vs[32][64];
    __shared__ float Ss[64][33];
    __shared__ float m_s[64], l_s[64], a_s[64];

    const int tid = threadIdx.x;
    const int qt  = blockIdx.x;
    const int h   = blockIdx.y;
    const int b   = blockIdx.z;
    const int ty  = tid >> 4;   // 0..15 -> 4 rows
    const int tx  = tid & 15;   // 0..15

    const float* base  = qkv + (size_t)b * T_ * 3 * C_ + h * D_;
    const float* kbase = base + C_;
    const float* vbase = base + 2 * C_;

    // load Q tile [64 x 64]
#pragma unroll
    for (int i = 0; i < 4; i++) {
        int lin = tid + i * 256;        // 0..1023
        int r = lin >> 4;               // 0..63
        int d = (lin & 15) * 4;
        float4 v = *(const float4*)(base + (size_t)(qt * 64 + r) * 3 * C_ + d);
        Qs[r][d + 0] = v.x; Qs[r][d + 1] = v.y;
        Qs[r][d + 2] = v.z; Qs[r][d + 3] = v.w;
    }
    if (tid < 64) { m_s[tid] = -INFINITY; l_s[tid] = 0.f; }

    float O[4][4];
#pragma unroll
    for (int i = 0; i < 4; i++)
#pragma unroll
        for (int j = 0; j < 4; j++) O[i][j] = 0.f;

    const int ntiles = qt * 2 + 2;     // keys 0 .. qt*64+63
    for (int jt = 0; jt < ntiles; jt++) {
        __syncthreads();
        // load K,V tiles [32 x 64]
#pragma unroll
        for (int i = 0; i < 2; i++) {
            int lin = tid + i * 256;    // 0..511
            int r = lin >> 4;           // 0..31
            int d = (lin & 15) * 4;
            size_t roff = (size_t)(jt * 32 + r) * 3 * C_ + d;
            float4 kv = *(const float4*)(kbase + roff);
            Ks[r][d + 0] = kv.x; Ks[r][d + 1] = kv.y;
            Ks[r][d + 2] = kv.z; Ks[r][d + 3] = kv.w;
            *(float4*)&Vs[r][d] = *(const float4*)(vbase + roff);
        }
        __syncthreads();

        // S[64x32] = (Q @ K^T) * 0.125, thread owns 4 rows x 2 cols
        float s[4][2];
#pragma unroll
        for (int i = 0; i < 4; i++) { s[i][0] = 0.f; s[i][1] = 0.f; }
#pragma unroll
        for (int d = 0; d < 64; d++) {
            float a0 = Qs[ty * 4 + 0][d], a1 = Qs[ty * 4 + 1][d];
            float a2 = Qs[ty * 4 + 2][d], a3 = Qs[ty * 4 + 3][d];
            float b0 = Ks[tx * 2 + 0][d], b1 = Ks[tx * 2 + 1][d];
            s[0][0] = fmaf(a0, b0, s[0][0]); s[0][1] = fmaf(a0, b1, s[0][1]);
            s[1][0] = fmaf(a1, b0, s[1][0]); s[1][1] = fmaf(a1, b1, s[1][1]);
            s[2][0] = fmaf(a2, b0, s[2][0]); s[2][1] = fmaf(a2, b1, s[2][1]);
            s[3][0] = fmaf(a3, b0, s[3][0]); s[3][1] = fmaf(a3, b1, s[3][1]);
        }
#pragma unroll
        for (int i = 0; i < 4; i++) {
            int qg = qt * 64 + ty * 4 + i;
#pragma unroll
            for (int j = 0; j < 2; j++) {
                int kg = jt * 32 + tx * 2 + j;
                Ss[ty * 4 + i][tx * 2 + j] = (kg <= qg) ? s[i][j] * 0.125f : -1e30f;
            }
        }
        __syncthreads();

        // online softmax per query row (threads 0..63)
        if (tid < 64) {
            int r = tid;
            float mold = m_s[r];
            float mx = mold;
#pragma unroll
            for (int kk = 0; kk < 32; kk++) mx = fmaxf(mx, Ss[r][kk]);
            float alpha = __expf(mold - mx);   // tile 0: exp(-inf)=0
            float ls = 0.f;
#pragma unroll
            for (int kk = 0; kk < 32; kk++) {
                float e = __expf(Ss[r][kk] - mx);
                Ss[r][kk] = e;
                ls += e;
            }
            m_s[r] = mx;
            l_s[r] = l_s[r] * alpha + ls;
            a_s[r] = alpha;
        }
        __syncthreads();

        // O = O*alpha + P @ V, thread owns 4 rows x 4 dims
#pragma unroll
        for (int i = 0; i < 4; i++) {
            float al = a_s[ty * 4 + i];
#pragma unroll
            for (int j = 0; j < 4; j++) O[i][j] *= al;
        }
#pragma unroll
        for (int kk = 0; kk < 32; kk++) {
            float4 v = *(const float4*)&Vs[kk][tx * 4];
            float p0 = Ss[ty * 4 + 0][kk], p1 = Ss[ty * 4 + 1][kk];
            float p2 = Ss[ty * 4 + 2][kk], p3 = Ss[ty * 4 + 3][kk];
            O[0][0] = fmaf(p0, v.x, O[0][0]); O[0][1] = fmaf(p0, v.y, O[0][1]);
            O[0][2] = fmaf(p0, v.z, O[0][2]); O[0][3] = fmaf(p0, v.w, O[0][3]);
            O[1][0] = fmaf(p1, v.x, O[1][0]); O[1][1] = fmaf(p1, v.y, O[1][1]);
            O[1][2] = fmaf(p1, v.z, O[1][2]); O[1][3] = fmaf(p1, v.w, O[1][3]);
            O[2][0] = fmaf(p2, v.x, O[2][0]); O[2][1] = fmaf(p2, v.y, O[2][1]);
            O[2][2] = fmaf(p2, v.z, O[2][2]); O[2][3] = fmaf(p2, v.w, O[2][3]);
            O[3][0] = fmaf(p3, v.x, O[3][0]); O[3][1] = fmaf(p3, v.y, O[3][1]);
            O[3][2] = fmaf(p3, v.z, O[3][2]); O[3][3] = fmaf(p3, v.w, O[3][3]);
        }
    }

    // write y[B,T,C]
    float* yb = y + (size_t)b * T_ * C_ + h * D_;
#pragma unroll
    for (int i = 0; i < 4; i++) {
        float inv = 1.f / l_s[ty * 4 + i];
        float4 o;
        o.x = O[i][0] * inv; o.y = O[i][1] * inv;
        o.z = O[i][2] * inv; o.w = O[i][3] * inv;
        *(float4*)(yb + (size_t)(qt * 64 + ty * 4 + i) * C_ + tx * 4) = o;
    }
}

// ---------------- residual add + LayerNorm (row of 1024) -------------------
__global__ void __launch_bounds__(256) add_ln_kernel(
    const float* __restrict__ a, const float* __restrict__ bres,
    const float* __restrict__ g, const float* __restrict__ beta,
    float* __restrict__ out)
{
    const int row = blockIdx.x;
    const int tid = threadIdx.x;      // 256 threads, 4 floats each

    const float4 av = ((const float4*)(a    + (size_t)row * C_))[tid];
    const float4 bv = ((const float4*)(bres + (size_t)row * C_))[tid];
    float4 v = make_float4(av.x + bv.x, av.y + bv.y, av.z + bv.z, av.w + bv.w);

    float s  = v.x + v.y + v.z + v.w;
    float sq = v.x * v.x + v.y * v.y + v.z * v.z + v.w * v.w;
#pragma unroll
    for (int off = 16; off; off >>= 1) {
        s  += __shfl_xor_sync(0xffffffffu, s,  off);
        sq += __shfl_xor_sync(0xffffffffu, sq, off);
    }
    __shared__ float ws[8], wsq[8];
    if ((tid & 31) == 0) { ws[tid >> 5] = s; wsq[tid >> 5] = sq; }
    __syncthreads();
    float tot = 0.f, totq = 0.f;
#pragma unroll
    for (int i = 0; i < 8; i++) { tot += ws[i]; totq += wsq[i]; }

    const float mu   = tot * (1.0f / C_);
    const float var  = totq * (1.0f / C_) - mu * mu;
    const float rstd = rsqrtf(var + LN_EPS);

    const float4 gv = ((const float4*)g)[tid];
    const float4 be = ((const float4*)beta)[tid];
    float4 o;
    o.x = (v.x - mu) * rstd * gv.x + be.x;
    o.y = (v.y - mu) * rstd * gv.y + be.y;
    o.z = (v.z - mu) * rstd * gv.z + be.z;
    o.w = (v.w - mu) * rstd * gv.w + be.w;
    ((float4*)(out + (size_t)row * C_))[tid] = o;
}

// ---------------- launcher --------------------------------------------------
extern "C" void kernel_launch(void* const* d_in, const int* in_sizes, int n_in,
                              void* d_out, int out_size)
{
    const float* x     = (const float*)d_in[0];
    const float* w_qkv = (const float*)d_in[1];
    const float* b_qkv = (const float*)d_in[2];
    const float* ln1_g = (const float*)d_in[3];
    const float* ln1_b = (const float*)d_in[4];
    const float* w_fc1 = (const float*)d_in[5];
    const float* b_fc1 = (const float*)d_in[6];
    const float* w_fc2 = (const float*)d_in[7];
    const float* b_fc2 = (const float*)d_in[8];
    const float* ln2_g = (const float*)d_in[9];
    const float* ln2_b = (const float*)d_in[10];
    float* out = (float*)d_out;

    float *qkv, *att, *x1, *hb, *mlp;
    cudaGetSymbolAddress((void**)&qkv, g_qkv);
    cudaGetSymbolAddress((void**)&att, g_att);
    cudaGetSymbolAddress((void**)&x1,  g_x1);
    cudaGetSymbolAddress((void**)&hb,  g_hb);
    cudaGetSymbolAddress((void**)&mlp, g_mlp);

    // qkv = x @ w_qkv + b_qkv
    gemm_bias<false><<<dim3(3 * C_ / 128, M_ / 128), 256>>>(
        x, w_qkv, b_qkv, qkv, M_, 3 * C_, C_);

    // causal attention
    attn_kernel<<<dim3(T_ / 64, H_, B_), 256>>>(qkv, att);

    // x1 = LN1(x + att)
    add_ln_kernel<<<M_, 256>>>(x, att, ln1_g, ln1_b, x1);

    // h = gelu(x1 @ w_fc1 + b_fc1)
    gemm_bias<true><<<dim3(4 * C_ / 128, M_ / 128), 256>>>(
        x1, w_fc1, b_fc1, hb, M_, 4 * C_, C_);

    // mlp = h @ w_fc2 + b_fc2
    gemm_bias<false><<<dim3(C_ / 128, M_ / 128), 256>>>(
        hb, w_fc2, b_fc2, mlp, M_, C_, 4 * C_);

    // out = LN2(x1 + mlp)
    add_ln_kernel<<<M_, 256>>>(x1, mlp, ln2_g, ln2_b, out);
}

// round 4
// speedup vs baseline: 1.8237x; 1.8237x over previous
#include <cuda_runtime.h>
#include <cuda_bf16.h>
#include <math.h>
#include <stdint.h>

#define B_   4
#define T_   2048
#define C_   1024
#define H_   16
#define D_   64
#define M_   (B_ * T_)           // 8192 rows
#define LN_EPS 1e-5f

// ---------------- scratch (static device globals; no allocation) -----------
__device__ __align__(128) float g_qkv[(size_t)M_ * 3 * C_];
__device__ __align__(128) float g_att[(size_t)M_ * C_];
__device__ __align__(128) float g_x1 [(size_t)M_ * C_];
__device__ __align__(128) float g_hb [(size_t)M_ * 4 * C_];
__device__ __align__(128) float g_mlp[(size_t)M_ * C_];
__device__ __align__(128) __nv_bfloat16 g_ah[(size_t)M_ * 4 * C_];       // A hi [M,K]
__device__ __align__(128) __nv_bfloat16 g_al[(size_t)M_ * 4 * C_];       // A lo
__device__ __align__(128) __nv_bfloat16 g_bh[(size_t)4 * C_ * C_];       // B hi [N,K]
__device__ __align__(128) __nv_bfloat16 g_bl[(size_t)4 * C_ * C_];       // B lo

__device__ __forceinline__ float gelu_exact(float x) {
    return 0.5f * x * (1.0f + erff(x * 0.70710678118654752440f));
}

// ---------------- PTX helpers ----------------------------------------------
__device__ __forceinline__ uint32_t smem_u32(const void* p) {
    uint32_t a;
    asm("{ .reg .u64 t; cvta.to.shared.u64 t, %1; cvt.u32.u64 %0, t; }" : "=r"(a) : "l"(p));
    return a;
}
#define CP16(s, g) asm volatile("cp.async.cg.shared.global [%0], [%1], 16;" :: "r"(s), "l"(g))
#define CP_COMMIT() asm volatile("cp.async.commit_group;" ::: "memory")
#define CP_WAIT1()  asm volatile("cp.async.wait_group 1;" ::: "memory")

__device__ __forceinline__ void ldsm4(uint32_t& r0, uint32_t& r1,
                                      uint32_t& r2, uint32_t& r3, uint32_t addr) {
    asm volatile("ldmatrix.sync.aligned.m8n8.x4.shared.b16 {%0,%1,%2,%3}, [%4];"
                 : "=r"(r0), "=r"(r1), "=r"(r2), "=r"(r3) : "r"(addr));
}
#define MMA16816(c, a, b)                                                     \
    asm volatile("mma.sync.aligned.m16n8k16.row.col.f32.bf16.bf16.f32 "       \
                 "{%0,%1,%2,%3}, {%4,%5,%6,%7}, {%8,%9}, {%0,%1,%2,%3};"      \
                 : "+f"((c)[0]), "+f"((c)[1]), "+f"((c)[2]), "+f"((c)[3])     \
                 : "r"((a)[0]), "r"((a)[1]), "r"((a)[2]), "r"((a)[3]),        \
                   "r"((b)[0]), "r"((b)[1]))

// ---------------- split kernels --------------------------------------------
__global__ void __launch_bounds__(256) split_act(
    const float* __restrict__ X, __nv_bfloat16* __restrict__ Hh,
    __nv_bfloat16* __restrict__ Ll, size_t n4)
{
    size_t i = (size_t)blockIdx.x * blockDim.x + threadIdx.x;
    if (i >= n4) return;
    float4 v = ((const float4*)X)[i];
    __nv_bfloat16 h0 = __float2bfloat16(v.x), h1 = __float2bfloat16(v.y);
    __nv_bfloat16 h2 = __float2bfloat16(v.z), h3 = __float2bfloat16(v.w);
    __nv_bfloat16 l0 = __float2bfloat16(v.x - __bfloat162float(h0));
    __nv_bfloat16 l1 = __float2bfloat16(v.y - __bfloat162float(h1));
    __nv_bfloat16 l2 = __float2bfloat16(v.z - __bfloat162float(h2));
    __nv_bfloat16 l3 = __float2bfloat16(v.w - __bfloat162float(h3));
    ((__nv_bfloat162*)Hh)[2 * i]     = __nv_bfloat162(h0, h1);
    ((__nv_bfloat162*)Hh)[2 * i + 1] = __nv_bfloat162(h2, h3);
    ((__nv_bfloat162*)Ll)[2 * i]     = __nv_bfloat162(l0, l1);
    ((__nv_bfloat162*)Ll)[2 * i + 1] = __nv_bfloat162(l2, l3);
}

// W [K,N] fp32 -> Bh/Bl [N,K] bf16 (transpose + split)
__global__ void __launch_bounds__(256) split_w_t(
    const float* __restrict__ W, __nv_bfloat16* __restrict__ Bh,
    __nv_bfloat16* __restrict__ Bl, int K, int N)
{
    __shared__ float t[32][33];
    const int tx = threadIdx.x, ty = threadIdx.y;   // block (32,8)
    const int n0 = blockIdx.x * 32, k0 = blockIdx.y * 32;
#pragma unroll
    for (int r = 0; r < 4; r++)
        t[ty + r * 8][tx] = W[(size_t)(k0 + ty + r * 8) * N + n0 + tx];
    __syncthreads();
#pragma unroll
    for (int r = 0; r < 4; r++) {
        int nn = ty + r * 8;
        float v = t[tx][nn];                       // = W[k0+tx][n0+nn]
        __nv_bfloat16 h = __float2bfloat16(v);
        __nv_bfloat16 l = __float2bfloat16(v - __bfloat162float(h));
        size_t o = (size_t)(n0 + nn) * K + k0 + tx;
        Bh[o] = h; Bl[o] = l;
    }
}

// ---------------- HMMA split-bf16 GEMM --------------------------------------
// C[M,N] = Ah@Bh^T + Al@Bh^T + Ah@Bl^T + bias   (fp32 accum, fused phases)
// Tile 128x128, BK=32, 8 warps (2m x 4n -> warp tile 64x32), 3-stage cp.async.
// SMEM rows padded to 80B (32 bf16 + 16B) -> ldmatrix conflict-free.
#define GM_BK       32
#define GM_ROWB     80                     // padded row bytes
#define GM_OP       (128 * GM_ROWB)        // 10240 B per operand tile
#define GM_STAGE    (4 * GM_OP)            // Ah,Al,Bh,Bl = 40960 B
#define GM_SMEM     (3 * GM_STAGE)         // 122880 B

template <bool GELU>
__global__ void __launch_bounds__(256) gemm_mma(
    const __nv_bfloat16* __restrict__ Ah, const __nv_bfloat16* __restrict__ Al,
    const __nv_bfloat16* __restrict__ Bh, const __nv_bfloat16* __restrict__ Bl,
    const float* __restrict__ bias, float* __restrict__ Cmat, int N, int K)
{
    extern __shared__ char smem[];
    const uint32_t sb = smem_u32(smem);
    const int tid  = threadIdx.x;
    const int lane = tid & 31;
    const int wid  = tid >> 5;
    const int m0 = blockIdx.y * 128;
    const int n0 = blockIdx.x * 128;
    const int wm = (wid >> 2) * 64;        // warp m offset in tile
    const int wn = (wid & 3) * 32;         // warp n offset in tile

    const int nch = K / GM_BK;

    auto load_chunk = [&](int c) {
        const int kk = c * GM_BK;
        const uint32_t st = sb + (c % 3) * GM_STAGE;
#pragma unroll
        for (int i = 0; i < 2; i++) {
            int u = tid + i * 256;                 // 0..511
            int r = u >> 2, cc = u & 3;
            uint32_t so = r * GM_ROWB + cc * 16;
            size_t ga = (size_t)(m0 + r) * K + kk + cc * 8;
            size_t gb = (size_t)(n0 + r) * K + kk + cc * 8;
            CP16(st + 0 * GM_OP + so, Ah + ga);
            CP16(st + 1 * GM_OP + so, Al + ga);
            CP16(st + 2 * GM_OP + so, Bh + gb);
            CP16(st + 3 * GM_OP + so, Bl + gb);
        }
    };

    float acc[4][4][4];
#pragma unroll
    for (int i = 0; i < 4; i++)
#pragma unroll
        for (int j = 0; j < 4; j++)
#pragma unroll
            for (int t = 0; t < 4; t++) acc[i][j][t] = 0.f;

    load_chunk(0); CP_COMMIT();
    load_chunk(1); CP_COMMIT();

    // per-lane ldmatrix addressing
    const int a_row = lane & 15;                   // + 16B col for lanes 16-31
    const int a_off = (lane >> 4) * 16;
    const int b_row = (lane & 7) + ((lane >> 4) << 3);
    const int b_off = ((lane >> 3) & 1) * 16;

    for (int k = 0; k < nch; k++) {
        CP_WAIT1();
        __syncthreads();
        if (k + 2 < nch) { load_chunk(k + 2); CP_COMMIT(); }

        const uint32_t stA = sb + (k % 3) * GM_STAGE;
        const uint32_t stB = stA + 2 * GM_OP;

#pragma unroll
        for (int ks = 0; ks < 2; ks++) {
            uint32_t ah[4][4], al[4][4], bh[4][2], bl[4][2];
#pragma unroll
            for (int mb = 0; mb < 4; mb++) {
                uint32_t ad = stA + (wm + mb * 16 + a_row) * GM_ROWB + ks * 32 + a_off;
                ldsm4(ah[mb][0], ah[mb][1], ah[mb][2], ah[mb][3], ad);
                ldsm4(al[mb][0], al[mb][1], al[mb][2], al[mb][3], ad + GM_OP);
            }
#pragma unroll
            for (int nb = 0; nb < 2; nb++) {
                uint32_t bd = stB + (wn + nb * 16 + b_row) * GM_ROWB + ks * 32 + b_off;
                uint32_t r0, r1, r2, r3;
                ldsm4(r0, r1, r2, r3, bd);
                bh[nb * 2][0] = r0; bh[nb * 2][1] = r1;
                bh[nb * 2 + 1][0] = r2; bh[nb * 2 + 1][1] = r3;
                ldsm4(r0, r1, r2, r3, bd + GM_OP);
                bl[nb * 2][0] = r0; bl[nb * 2][1] = r1;
                bl[nb * 2 + 1][0] = r2; bl[nb * 2 + 1][1] = r3;
            }
#pragma unroll
            for (int mb = 0; mb < 4; mb++)
#pragma unroll
                for (int nb = 0; nb < 4; nb++) {
                    MMA16816(acc[mb][nb], ah[mb], bh[nb]);
                    MMA16816(acc[mb][nb], al[mb], bh[nb]);
                    MMA16816(acc[mb][nb], ah[mb], bl[nb]);
                }
        }
    }

    // ---- epilogue ----
    const int gr = lane >> 2;
    const int gc = (lane & 3) * 2;
#pragma unroll
    for (int mb = 0; mb < 4; mb++) {
#pragma unroll
        for (int nb = 0; nb < 4; nb++) {
            int row = m0 + wm + mb * 16 + gr;
            int col = n0 + wn + nb * 8 + gc;
            float b0 = __ldg(&bias[col]), b1 = __ldg(&bias[col + 1]);
            float v0 = acc[mb][nb][0] + b0, v1 = acc[mb][nb][1] + b1;
            float v2 = acc[mb][nb][2] + b0, v3 = acc[mb][nb][3] + b1;
            if (GELU) {
                v0 = gelu_exact(v0); v1 = gelu_exact(v1);
                v2 = gelu_exact(v2); v3 = gelu_exact(v3);
            }
            *(float2*)(Cmat + (size_t)row * N + col)       = make_float2(v0, v1);
            *(float2*)(Cmat + (size_t)(row + 8) * N + col) = make_float2(v2, v3);
        }
    }
}

// ---------------- causal flash attention (FFMA, as in R1) ------------------
__global__ void __launch_bounds__(256) attn_kernel(
    const float* __restrict__ qkv, float* __restrict__ y)
{
    __shared__ float Qs[64][65];
    __shared__ float Ks[32][65];
    __shared__ float Vs[32][64];
    __shared__ float Ss[64][33];
    __shared__ float m_s[64], l_s[64], a_s[64];

    const int tid = threadIdx.x;
    const int qt  = blockIdx.x;
    const int h   = blockIdx.y;
    const int b   = blockIdx.z;
    const int ty  = tid >> 4;
    const int tx  = tid & 15;

    const float* base  = qkv + (size_t)b * T_ * 3 * C_ + h * D_;
    const float* kbase = base + C_;
    const float* vbase = base + 2 * C_;

#pragma unroll
    for (int i = 0; i < 4; i++) {
        int lin = tid + i * 256;
        int r = lin >> 4;
        int d = (lin & 15) * 4;
        float4 v = *(const float4*)(base + (size_t)(qt * 64 + r) * 3 * C_ + d);
        Qs[r][d + 0] = v.x; Qs[r][d + 1] = v.y;
        Qs[r][d + 2] = v.z; Qs[r][d + 3] = v.w;
    }
    if (tid < 64) { m_s[tid] = -INFINITY; l_s[tid] = 0.f; }

    float O[4][4];
#pragma unroll
    for (int i = 0; i < 4; i++)
#pragma unroll
        for (int j = 0; j < 4; j++) O[i][j] = 0.f;

    const int ntiles = qt * 2 + 2;
    for (int jt = 0; jt < ntiles; jt++) {
        __syncthreads();
#pragma unroll
        for (int i = 0; i < 2; i++) {
            int lin = tid + i * 256;
            int r = lin >> 4;
            int d = (lin & 15) * 4;
            size_t roff = (size_t)(jt * 32 + r) * 3 * C_ + d;
            float4 kv = *(const float4*)(kbase + roff);
            Ks[r][d + 0] = kv.x; Ks[r][d + 1] = kv.y;
            Ks[r][d + 2] = kv.z; Ks[r][d + 3] = kv.w;
            *(float4*)&Vs[r][d] = *(const float4*)(vbase + roff);
        }
        __syncthreads();

        float s[4][2];
#pragma unroll
        for (int i = 0; i < 4; i++) { s[i][0] = 0.f; s[i][1] = 0.f; }
#pragma unroll
        for (int d = 0; d < 64; d++) {
            float a0 = Qs[ty * 4 + 0][d], a1 = Qs[ty * 4 + 1][d];
            float a2 = Qs[ty * 4 + 2][d], a3 = Qs[ty * 4 + 3][d];
            float b0 = Ks[tx * 2 + 0][d], b1 = Ks[tx * 2 + 1][d];
            s[0][0] = fmaf(a0, b0, s[0][0]); s[0][1] = fmaf(a0, b1, s[0][1]);
            s[1][0] = fmaf(a1, b0, s[1][0]); s[1][1] = fmaf(a1, b1, s[1][1]);
            s[2][0] = fmaf(a2, b0, s[2][0]); s[2][1] = fmaf(a2, b1, s[2][1]);
            s[3][0] = fmaf(a3, b0, s[3][0]); s[3][1] = fmaf(a3, b1, s[3][1]);
        }
#pragma unroll
        for (int i = 0; i < 4; i++) {
            int qg = qt * 64 + ty * 4 + i;
#pragma unroll
            for (int j = 0; j < 2; j++) {
                int kg = jt * 32 + tx * 2 + j;
                Ss[ty * 4 + i][tx * 2 + j] = (kg <= qg) ? s[i][j] * 0.125f : -1e30f;
            }
        }
        __syncthreads();

        if (tid < 64) {
            int r = tid;
            float mold = m_s[r];
            float mx = mold;
#pragma unroll
            for (int kk = 0; kk < 32; kk++) mx = fmaxf(mx, Ss[r][kk]);
            float alpha = __expf(mold - mx);
            float ls = 0.f;
#pragma unroll
            for (int kk = 0; kk < 32; kk++) {
                float e = __expf(Ss[r][kk] - mx);
                Ss[r][kk] = e;
                ls += e;
            }
            m_s[r] = mx;
            l_s[r] = l_s[r] * alpha + ls;
            a_s[r] = alpha;
        }
        __syncthreads();

#pragma unroll
        for (int i = 0; i < 4; i++) {
            float al = a_s[ty * 4 + i];
#pragma unroll
            for (int j = 0; j < 4; j++) O[i][j] *= al;
        }
#pragma unroll
        for (int kk = 0; kk < 32; kk++) {
            float4 v = *(const float4*)&Vs[kk][tx * 4];
            float p0 = Ss[ty * 4 + 0][kk], p1 = Ss[ty * 4 + 1][kk];
            float p2 = Ss[ty * 4 + 2][kk], p3 = Ss[ty * 4 + 3][kk];
            O[0][0] = fmaf(p0, v.x, O[0][0]); O[0][1] = fmaf(p0, v.y, O[0][1]);
            O[0][2] = fmaf(p0, v.z, O[0][2]); O[0][3] = fmaf(p0, v.w, O[0][3]);
            O[1][0] = fmaf(p1, v.x, O[1][0]); O[1][1] = fmaf(p1, v.y, O[1][1]);
            O[1][2] = fmaf(p1, v.z, O[1][2]); O[1][3] = fmaf(p1, v.w, O[1][3]);
            O[2][0] = fmaf(p2, v.x, O[2][0]); O[2][1] = fmaf(p2, v.y, O[2][1]);
            O[2][2] = fmaf(p2, v.z, O[2][2]); O[2][3] = fmaf(p2, v.w, O[2][3]);
            O[3][0] = fmaf(p3, v.x, O[3][0]); O[3][1] = fmaf(p3, v.y, O[3][1]);
            O[3][2] = fmaf(p3, v.z, O[3][2]); O[3][3] = fmaf(p3, v.w, O[3][3]);
        }
    }

    float* yb = y + (size_t)b * T_ * C_ + h * D_;
#pragma unroll
    for (int i = 0; i < 4; i++) {
        float inv = 1.f / l_s[ty * 4 + i];
        float4 o;
        o.x = O[i][0] * inv; o.y = O[i][1] * inv;
        o.z = O[i][2] * inv; o.w = O[i][3] * inv;
        *(float4*)(yb + (size_t)(qt * 64 + ty * 4 + i) * C_ + tx * 4) = o;
    }
}

// ---------------- residual add + LayerNorm ---------------------------------
__global__ void __launch_bounds__(256) add_ln_kernel(
    const float* __restrict__ a, const float* __restrict__ bres,
    const float* __restrict__ g, const float* __restrict__ beta,
    float* __restrict__ out)
{
    const int row = blockIdx.x;
    const int tid = threadIdx.x;

    const float4 av = ((const float4*)(a    + (size_t)row * C_))[tid];
    const float4 bv = ((const float4*)(bres + (size_t)row * C_))[tid];
    float4 v = make_float4(av.x + bv.x, av.y + bv.y, av.z + bv.z, av.w + bv.w);

    float s  = v.x + v.y + v.z + v.w;
    float sq = v.x * v.x + v.y * v.y + v.z * v.z + v.w * v.w;
#pragma unroll
    for (int off = 16; off; off >>= 1) {
        s  += __shfl_xor_sync(0xffffffffu, s,  off);
        sq += __shfl_xor_sync(0xffffffffu, sq, off);
    }
    __shared__ float ws[8], wsq[8];
    if ((tid & 31) == 0) { ws[tid >> 5] = s; wsq[tid >> 5] = sq; }
    __syncthreads();
    float tot = 0.f, totq = 0.f;
#pragma unroll
    for (int i = 0; i < 8; i++) { tot += ws[i]; totq += wsq[i]; }

    const float mu   = tot * (1.0f / C_);
    const float var  = totq * (1.0f / C_) - mu * mu;
    const float rstd = rsqrtf(var + LN_EPS);

    const float4 gv = ((const float4*)g)[tid];
    const float4 be = ((const float4*)beta)[tid];
    float4 o;
    o.x = (v.x - mu) * rstd * gv.x + be.x;
    o.y = (v.y - mu) * rstd * gv.y + be.y;
    o.z = (v.z - mu) * rstd * gv.z + be.z;
    o.w = (v.w - mu) * rstd * gv.w + be.w;
    ((float4*)(out + (size_t)row * C_))[tid] = o;
}

// ---------------- launcher --------------------------------------------------
extern "C" void kernel_launch(void* const* d_in, const int* in_sizes, int n_in,
                              void* d_out, int out_size)
{
    const float* x     = (const float*)d_in[0];
    const float* w_qkv = (const float*)d_in[1];
    const float* b_qkv = (const float*)d_in[2];
    const float* ln1_g = (const float*)d_in[3];
    const float* ln1_b = (const float*)d_in[4];
    const float* w_fc1 = (const float*)d_in[5];
    const float* b_fc1 = (const float*)d_in[6];
    const float* w_fc2 = (const float*)d_in[7];
    const float* b_fc2 = (const float*)d_in[8];
    const float* ln2_g = (const float*)d_in[9];
    const float* ln2_b = (const float*)d_in[10];
    float* out = (float*)d_out;

    float *qkv, *att, *x1, *hb, *mlp;
    __nv_bfloat16 *ah, *al, *bh, *bl;
    cudaGetSymbolAddress((void**)&qkv, g_qkv);
    cudaGetSymbolAddress((void**)&att, g_att);
    cudaGetSymbolAddress((void**)&x1,  g_x1);
    cudaGetSymbolAddress((void**)&hb,  g_hb);
    cudaGetSymbolAddress((void**)&mlp, g_mlp);
    cudaGetSymbolAddress((void**)&ah,  g_ah);
    cudaGetSymbolAddress((void**)&al,  g_al);
    cudaGetSymbolAddress((void**)&bh,  g_bh);
    cudaGetSymbolAddress((void**)&bl,  g_bl);

    cudaFuncSetAttribute(gemm_mma<false>, cudaFuncAttributeMaxDynamicSharedMemorySize, GM_SMEM);
    cudaFuncSetAttribute(gemm_mma<true>,  cudaFuncAttributeMaxDynamicSharedMemorySize, GM_SMEM);

    // ---- QKV = x @ w_qkv + b ----
    split_act<<<(M_ * C_ / 4 + 255) / 256, 256>>>(x, ah, al, (size_t)M_ * C_ / 4);
    split_w_t<<<dim3(3 * C_ / 32, C_ / 32), dim3(32, 8)>>>(w_qkv, bh, bl, C_, 3 * C_);
    gemm_mma<false><<<dim3(3 * C_ / 128, M_ / 128), 256, GM_SMEM>>>(
        ah, al, bh, bl, b_qkv, qkv, 3 * C_, C_);

    // ---- attention ----
    attn_kernel<<<dim3(T_ / 64, H_, B_), 256>>>(qkv, att);

    // ---- x1 = LN1(x + att) ----
    add_ln_kernel<<<M_, 256>>>(x, att, ln1_g, ln1_b, x1);

    // ---- h = gelu(x1 @ w_fc1 + b) ----
    split_act<<<(M_ * C_ / 4 + 255) / 256, 256>>>(x1, ah, al, (size_t)M_ * C_ / 4);
    split_w_t<<<dim3(4 * C_ / 32, C_ / 32), dim3(32, 8)>>>(w_fc1, bh, bl, C_, 4 * C_);
    gemm_mma<true><<<dim3(4 * C_ / 128, M_ / 128), 256, GM_SMEM>>>(
        ah, al, bh, bl, b_fc1, hb, 4 * C_, C_);

    // ---- mlp = h @ w_fc2 + b ----
    split_act<<<(M_ * 4 * C_ / 4 + 255) / 256, 256>>>(hb, ah, al, (size_t)M_ * 4 * C_ / 4);
    split_w_t<<<dim3(C_ / 32, 4 * C_ / 32), dim3(32, 8)>>>(w_fc2, bh, bl, 4 * C_, C_);
    gemm_mma<false><<<dim3(C_ / 128, M_ / 128), 256, GM_SMEM>>>(
        ah, al, bh, bl, b_fc2, mlp, C_, 4 * C_);

    // ---- out = LN2(x1 + mlp) ----
    add_ln_kernel<<<M_, 256>>>(x1, mlp, ln2_g, ln2_b, out);
}

// round 5
// speedup vs baseline: 2.6584x; 1.4577x over previous
#include <cuda_runtime.h>
#include <cuda_bf16.h>
#include <math.h>
#include <stdint.h>

#define B_   4
#define T_   2048
#define C_   1024
#define H_   16
#define D_   64
#define M_   (B_ * T_)           // 8192 rows
#define LN_EPS 1e-5f

// ---------------- scratch (static device globals; no allocation) -----------
__device__ __align__(128) float g_att[(size_t)M_ * C_];
__device__ __align__(128) float g_x1 [(size_t)M_ * C_];
__device__ __align__(128) float g_mlp[(size_t)M_ * C_];
__device__ __align__(128) __nv_bfloat16 g_qkvh[(size_t)M_ * 3 * C_];
__device__ __align__(128) __nv_bfloat16 g_qkvl[(size_t)M_ * 3 * C_];
__device__ __align__(128) __nv_bfloat16 g_ah [(size_t)M_ * C_];       // A hi (x / x1)
__device__ __align__(128) __nv_bfloat16 g_al [(size_t)M_ * C_];
__device__ __align__(128) __nv_bfloat16 g_ah2[(size_t)M_ * 4 * C_];   // gelu(h) hi
__device__ __align__(128) __nv_bfloat16 g_al2[(size_t)M_ * 4 * C_];
__device__ __align__(128) __nv_bfloat16 g_bh [(size_t)4 * C_ * C_];   // B hi [N,K]
__device__ __align__(128) __nv_bfloat16 g_bl [(size_t)4 * C_ * C_];

__device__ __forceinline__ float gelu_exact(float x) {
    return 0.5f * x * (1.0f + erff(x * 0.70710678118654752440f));
}

// ---------------- PTX helpers ----------------------------------------------
__device__ __forceinline__ uint32_t smem_u32(const void* p) {
    uint32_t a;
    asm("{ .reg .u64 t; cvta.to.shared.u64 t, %1; cvt.u32.u64 %0, t; }" : "=r"(a) : "l"(p));
    return a;
}
#define CP16(s, g) asm volatile("cp.async.cg.shared.global [%0], [%1], 16;" :: "r"(s), "l"(g))
#define CP_COMMIT() asm volatile("cp.async.commit_group;" ::: "memory")
#define CP_WAIT1()  asm volatile("cp.async.wait_group 1;" ::: "memory")
#define CP_WAIT0()  asm volatile("cp.async.wait_group 0;" ::: "memory")

__device__ __forceinline__ void ldsm4(uint32_t& r0, uint32_t& r1,
                                      uint32_t& r2, uint32_t& r3, uint32_t addr) {
    asm volatile("ldmatrix.sync.aligned.m8n8.x4.shared.b16 {%0,%1,%2,%3}, [%4];"
                 : "=r"(r0), "=r"(r1), "=r"(r2), "=r"(r3) : "r"(addr));
}
__device__ __forceinline__ void ldsm4t(uint32_t& r0, uint32_t& r1,
                                       uint32_t& r2, uint32_t& r3, uint32_t addr) {
    asm volatile("ldmatrix.sync.aligned.m8n8.x4.trans.shared.b16 {%0,%1,%2,%3}, [%4];"
                 : "=r"(r0), "=r"(r1), "=r"(r2), "=r"(r3) : "r"(addr));
}
#define MMA16816(c, a, b)                                                     \
    asm volatile("mma.sync.aligned.m16n8k16.row.col.f32.bf16.bf16.f32 "       \
                 "{%0,%1,%2,%3}, {%4,%5,%6,%7}, {%8,%9}, {%0,%1,%2,%3};"      \
                 : "+f"((c)[0]), "+f"((c)[1]), "+f"((c)[2]), "+f"((c)[3])     \
                 : "r"((a)[0]), "r"((a)[1]), "r"((a)[2]), "r"((a)[3]),        \
                   "r"((b)[0]), "r"((b)[1]))

// pack two f32 -> bf16x2 (lo half = first arg)
__device__ __forceinline__ uint32_t pack_bf16x2(float lo, float hi) {
    uint32_t r;
    asm("cvt.rn.bf16x2.f32 %0, %1, %2;" : "=r"(r) : "f"(hi), "f"(lo));
    return r;
}
// split (x,y) into hi bf16x2 + residual-lo bf16x2
__device__ __forceinline__ void split_pack2(float x, float y, uint32_t& hi, uint32_t& lo) {
    float hx = __bfloat162float(__float2bfloat16(x));
    float hy = __bfloat162float(__float2bfloat16(y));
    hi = pack_bf16x2(hx, hy);
    lo = pack_bf16x2(x - hx, y - hy);
}

// ---------------- split kernels --------------------------------------------
__global__ void __launch_bounds__(256) split_act(
    const float* __restrict__ X, __nv_bfloat16* __restrict__ Hh,
    __nv_bfloat16* __restrict__ Ll, size_t n4)
{
    size_t i = (size_t)blockIdx.x * blockDim.x + threadIdx.x;
    if (i >= n4) return;
    float4 v = ((const float4*)X)[i];
    uint32_t h0, l0, h1, l1;
    split_pack2(v.x, v.y, h0, l0);
    split_pack2(v.z, v.w, h1, l1);
    ((uint32_t*)Hh)[2 * i] = h0; ((uint32_t*)Hh)[2 * i + 1] = h1;
    ((uint32_t*)Ll)[2 * i] = l0; ((uint32_t*)Ll)[2 * i + 1] = l1;
}

// W [K,N] fp32 -> Bh/Bl [N,K] bf16 (transpose + split)
__global__ void __launch_bounds__(256) split_w_t(
    const float* __restrict__ W, __nv_bfloat16* __restrict__ Bh,
    __nv_bfloat16* __restrict__ Bl, int K, int N)
{
    __shared__ float t[32][33];
    const int tx = threadIdx.x, ty = threadIdx.y;   // block (32,8)
    const int n0 = blockIdx.x * 32, k0 = blockIdx.y * 32;
#pragma unroll
    for (int r = 0; r < 4; r++)
        t[ty + r * 8][tx] = W[(size_t)(k0 + ty + r * 8) * N + n0 + tx];
    __syncthreads();
#pragma unroll
    for (int r = 0; r < 4; r++) {
        int nn = ty + r * 8;
        float v = t[tx][nn];
        __nv_bfloat16 h = __float2bfloat16(v);
        __nv_bfloat16 l = __float2bfloat16(v - __bfloat162float(h));
        size_t o = (size_t)(n0 + nn) * K + k0 + tx;
        Bh[o] = h; Bl[o] = l;
    }
}

// ---------------- HMMA split-bf16 GEMM --------------------------------------
// C = Ah@Bh^T + Al@Bh^T + Ah@Bl^T + bias  (fp32 accum)
// MODE 0: fp32 out; MODE 1: split bf16 out, cols<C_ scaled 0.125 (QKV);
// MODE 2: gelu then split bf16 out.
#define GM_BK       32
#define GM_ROWB     80
#define GM_OP       (128 * GM_ROWB)
#define GM_STAGE    (4 * GM_OP)
#define GM_SMEM     (3 * GM_STAGE)

template <int MODE>
__global__ void __launch_bounds__(256) gemm_mma(
    const __nv_bfloat16* __restrict__ Ah, const __nv_bfloat16* __restrict__ Al,
    const __nv_bfloat16* __restrict__ Bh, const __nv_bfloat16* __restrict__ Bl,
    const float* __restrict__ bias, float* __restrict__ Cmat,
    __nv_bfloat16* __restrict__ Oh, __nv_bfloat16* __restrict__ Ol,
    int N, int K)
{
    extern __shared__ char smem[];
    const uint32_t sb = smem_u32(smem);
    const int tid  = threadIdx.x;
    const int lane = tid & 31;
    const int wid  = tid >> 5;
    const int m0 = blockIdx.y * 128;
    const int n0 = blockIdx.x * 128;
    const int wm = (wid >> 2) * 64;
    const int wn = (wid & 3) * 32;

    const int nch = K / GM_BK;

    auto load_chunk = [&](int c) {
        const int kk = c * GM_BK;
        const uint32_t st = sb + (c % 3) * GM_STAGE;
#pragma unroll
        for (int i = 0; i < 2; i++) {
            int u = tid + i * 256;
            int r = u >> 2, cc = u & 3;
            uint32_t so = r * GM_ROWB + cc * 16;
            size_t ga = (size_t)(m0 + r) * K + kk + cc * 8;
            size_t gb = (size_t)(n0 + r) * K + kk + cc * 8;
            CP16(st + 0 * GM_OP + so, Ah + ga);
            CP16(st + 1 * GM_OP + so, Al + ga);
            CP16(st + 2 * GM_OP + so, Bh + gb);
            CP16(st + 3 * GM_OP + so, Bl + gb);
        }
    };

    float acc[4][4][4];
#pragma unroll
    for (int i = 0; i < 4; i++)
#pragma unroll
        for (int j = 0; j < 4; j++)
#pragma unroll
            for (int t = 0; t < 4; t++) acc[i][j][t] = 0.f;

    load_chunk(0); CP_COMMIT();
    load_chunk(1); CP_COMMIT();

    const int a_row = lane & 15;
    const int a_off = (lane >> 4) * 16;
    const int b_row = (lane & 7) + ((lane >> 4) << 3);
    const int b_off = ((lane >> 3) & 1) * 16;

    for (int k = 0; k < nch; k++) {
        CP_WAIT1();
        __syncthreads();
        if (k + 2 < nch) { load_chunk(k + 2); CP_COMMIT(); }

        const uint32_t stA = sb + (k % 3) * GM_STAGE;
        const uint32_t stB = stA + 2 * GM_OP;

#pragma unroll
        for (int ks = 0; ks < 2; ks++) {
            uint32_t ah[4][4], al[4][4], bh[4][2], bl[4][2];
#pragma unroll
            for (int mb = 0; mb < 4; mb++) {
                uint32_t ad = stA + (wm + mb * 16 + a_row) * GM_ROWB + ks * 32 + a_off;
                ldsm4(ah[mb][0], ah[mb][1], ah[mb][2], ah[mb][3], ad);
                ldsm4(al[mb][0], al[mb][1], al[mb][2], al[mb][3], ad + GM_OP);
            }
#pragma unroll
            for (int nb = 0; nb < 2; nb++) {
                uint32_t bd = stB + (wn + nb * 16 + b_row) * GM_ROWB + ks * 32 + b_off;
                uint32_t r0, r1, r2, r3;
                ldsm4(r0, r1, r2, r3, bd);
                bh[nb * 2][0] = r0; bh[nb * 2][1] = r1;
                bh[nb * 2 + 1][0] = r2; bh[nb * 2 + 1][1] = r3;
                ldsm4(r0, r1, r2, r3, bd + GM_OP);
                bl[nb * 2][0] = r0; bl[nb * 2][1] = r1;
                bl[nb * 2 + 1][0] = r2; bl[nb * 2 + 1][1] = r3;
            }
#pragma unroll
            for (int mb = 0; mb < 4; mb++)
#pragma unroll
                for (int nb = 0; nb < 4; nb++) {
                    MMA16816(acc[mb][nb], ah[mb], bh[nb]);
                    MMA16816(acc[mb][nb], al[mb], bh[nb]);
                    MMA16816(acc[mb][nb], ah[mb], bl[nb]);
                }
        }
    }

    // ---- epilogue ----
    const int gr = lane >> 2;
    const int gc = (lane & 3) * 2;
#pragma unroll
    for (int mb = 0; mb < 4; mb++) {
#pragma unroll
        for (int nb = 0; nb < 4; nb++) {
            int row = m0 + wm + mb * 16 + gr;
            int col = n0 + wn + nb * 8 + gc;
            float b0 = __ldg(&bias[col]), b1 = __ldg(&bias[col + 1]);
            float v0 = acc[mb][nb][0] + b0, v1 = acc[mb][nb][1] + b1;
            float v2 = acc[mb][nb][2] + b0, v3 = acc[mb][nb][3] + b1;
            if (MODE == 0) {
                *(float2*)(Cmat + (size_t)row * N + col)       = make_float2(v0, v1);
                *(float2*)(Cmat + (size_t)(row + 8) * N + col) = make_float2(v2, v3);
            } else {
                if (MODE == 1 && col < C_) { v0 *= 0.125f; v1 *= 0.125f; v2 *= 0.125f; v3 *= 0.125f; }
                if (MODE == 2) {
                    v0 = gelu_exact(v0); v1 = gelu_exact(v1);
                    v2 = gelu_exact(v2); v3 = gelu_exact(v3);
                }
                uint32_t h01, l01, h23, l23;
                split_pack2(v0, v1, h01, l01);
                split_pack2(v2, v3, h23, l23);
                *(uint32_t*)(Oh + (size_t)row * N + col)       = h01;
                *(uint32_t*)(Ol + (size_t)row * N + col)       = l01;
                *(uint32_t*)(Oh + (size_t)(row + 8) * N + col) = h23;
                *(uint32_t*)(Ol + (size_t)(row + 8) * N + col) = l23;
            }
        }
    }
}

// ---------------- tensor-core causal flash attention ------------------------
// 64 queries per CTA (4 warps x 16 rows), 64-key tiles, split-bf16 MMAs.
#define AT_ROWB  144                     // 128B row + 16B pad
#define AT_T     (64 * AT_ROWB)          // 9216 per tensor tile
#define AT_STAGE (4 * AT_T)              // Kh,Kl,Vh,Vl
#define AT_SMEM  (2 * AT_T + 2 * AT_STAGE)   // Q(h,l) + 2 stages = 92160

__global__ void __launch_bounds__(128) attn_tc(
    const __nv_bfloat16* __restrict__ qkvh,
    const __nv_bfloat16* __restrict__ qkvl,
    float* __restrict__ y)
{
    extern __shared__ char smem[];
    const uint32_t sb = smem_u32(smem);
    const int tid = threadIdx.x, lane = tid & 31, wid = tid >> 5;
    const int qb = (int)gridDim.x - 1 - (int)blockIdx.x;   // big blocks first
    const int h = blockIdx.y, b = blockIdx.z;
    const int q0 = qb * 64;
    const int wq = wid * 16;
    const int gr = lane >> 2, gc = lane & 3;
    const int RS = 3 * C_;

    const __nv_bfloat16* qh = qkvh + (size_t)b * T_ * RS + h * D_;
    const __nv_bfloat16* ql = qkvl + (size_t)b * T_ * RS + h * D_;
    const __nv_bfloat16* kh = qh + C_;
    const __nv_bfloat16* kl = ql + C_;
    const __nv_bfloat16* vh = qh + 2 * C_;
    const __nv_bfloat16* vl = ql + 2 * C_;

    const uint32_t QH  = sb;
    const uint32_t ST0 = sb + 2 * AT_T;

    // load Q (hi/lo) tile: 64 rows x 128B each
#pragma unroll
    for (int i = 0; i < 8; i++) {
        const int t = i >> 2;
        int w = tid + (i & 3) * 128;       // 0..511
        int r = w >> 3, c = w & 7;
        const __nv_bfloat16* g = (t ? ql : qh) + (size_t)(q0 + r) * RS + c * 8;
        CP16(QH + t * AT_T + r * AT_ROWB + c * 16, g);
    }

    auto load_tile = [&](int kt, int bufsel) {
        uint32_t st = ST0 + bufsel * AT_STAGE;
#pragma unroll
        for (int i = 0; i < 16; i++) {
            const int t = i >> 2;
            int w = tid + (i & 3) * 128;
            int r = w >> 3, c = w & 7;
            const __nv_bfloat16* g =
                (t == 0 ? kh : t == 1 ? kl : t == 2 ? vh : vl)
                + (size_t)(kt * 64 + r) * RS + c * 8;
            CP16(st + t * AT_T + r * AT_ROWB + c * 16, g);
        }
    };
    load_tile(0, 0);
    CP_COMMIT();
    CP_WAIT0();
    __syncthreads();

    // Q fragments
    uint32_t qfh[4][4], qfl[4][4];
    const int a_row = lane & 15, a_off = (lane >> 4) * 16;
#pragma unroll
    for (int ks = 0; ks < 4; ks++) {
        uint32_t ad = QH + (wq + a_row) * AT_ROWB + ks * 32 + a_off;
        ldsm4(qfh[ks][0], qfh[ks][1], qfh[ks][2], qfh[ks][3], ad);
        ldsm4(qfl[ks][0], qfl[ks][1], qfl[ks][2], qfl[ks][3], ad + AT_T);
    }

    float Oacc[8][4];
#pragma unroll
    for (int i = 0; i < 8; i++)
#pragma unroll
        for (int j = 0; j < 4; j++) Oacc[i][j] = 0.f;
    float m0 = -1e30f, m1 = -1e30f, l0 = 0.f, l1 = 0.f;

    const int nt = qb + 1;
    const int b_row = (lane & 7) + ((lane >> 4) << 3);
    const int b_off = ((lane >> 3) & 1) * 16;
    const int v_row = (lane & 7) + ((lane >> 3) & 1) * 8;
    const int v_off = (lane >> 4) * 16;

    for (int kt = 0; kt < nt; kt++) {
        if (kt + 1 < nt) { load_tile(kt + 1, (kt + 1) & 1); CP_COMMIT(); }
        const uint32_t st = ST0 + (kt & 1) * AT_STAGE;

        // ---- S = Q @ K^T (3-term split) ----
        float sacc[8][4];
#pragma unroll
        for (int i = 0; i < 8; i++)
#pragma unroll
            for (int j = 0; j < 4; j++) sacc[i][j] = 0.f;

#pragma unroll
        for (int nbp = 0; nbp < 4; nbp++) {
#pragma unroll
            for (int ks = 0; ks < 4; ks++) {
                uint32_t kd = st + (nbp * 16 + b_row) * AT_ROWB + ks * 32 + b_off;
                uint32_t rh[4], rl[4];
                ldsm4(rh[0], rh[1], rh[2], rh[3], kd);
                ldsm4(rl[0], rl[1], rl[2], rl[3], kd + AT_T);
                uint32_t b0h[2] = {rh[0], rh[1]}, b1h[2] = {rh[2], rh[3]};
                uint32_t b0l[2] = {rl[0], rl[1]}, b1l[2] = {rl[2], rl[3]};
                MMA16816(sacc[2 * nbp],     qfh[ks], b0h);
                MMA16816(sacc[2 * nbp],     qfl[ks], b0h);
                MMA16816(sacc[2 * nbp],     qfh[ks], b0l);
                MMA16816(sacc[2 * nbp + 1], qfh[ks], b1h);
                MMA16816(sacc[2 * nbp + 1], qfl[ks], b1h);
                MMA16816(sacc[2 * nbp + 1], qfh[ks], b1l);
            }
        }

        // ---- causal mask (diagonal tile only) ----
        if (kt == qb) {
            const int qg0 = q0 + wq + gr, qg1 = qg0 + 8;
#pragma unroll
            for (int nb = 0; nb < 8; nb++) {
                int kg = kt * 64 + nb * 8 + 2 * gc;
                if (kg     > qg0) sacc[nb][0] = -1e30f;
                if (kg + 1 > qg0) sacc[nb][1] = -1e30f;
                if (kg     > qg1) sacc[nb][2] = -1e30f;
                if (kg + 1 > qg1) sacc[nb][3] = -1e30f;
            }
        }

        // ---- online softmax ----
        float mx0 = m0, mx1 = m1;
#pragma unroll
        for (int nb = 0; nb < 8; nb++) {
            mx0 = fmaxf(mx0, fmaxf(sacc[nb][0], sacc[nb][1]));
            mx1 = fmaxf(mx1, fmaxf(sacc[nb][2], sacc[nb][3]));
        }
        mx0 = fmaxf(mx0, __shfl_xor_sync(0xffffffffu, mx0, 1));
        mx0 = fmaxf(mx0, __shfl_xor_sync(0xffffffffu, mx0, 2));
        mx1 = fmaxf(mx1, __shfl_xor_sync(0xffffffffu, mx1, 1));
        mx1 = fmaxf(mx1, __shfl_xor_sync(0xffffffffu, mx1, 2));
        float al0 = __expf(m0 - mx0), al1 = __expf(m1 - mx1);
        m0 = mx0; m1 = mx1;
        float ls0 = 0.f, ls1 = 0.f;
#pragma unroll
        for (int nb = 0; nb < 8; nb++) {
            sacc[nb][0] = __expf(sacc[nb][0] - mx0); ls0 += sacc[nb][0];
            sacc[nb][1] = __expf(sacc[nb][1] - mx0); ls0 += sacc[nb][1];
            sacc[nb][2] = __expf(sacc[nb][2] - mx1); ls1 += sacc[nb][2];
            sacc[nb][3] = __expf(sacc[nb][3] - mx1); ls1 += sacc[nb][3];
        }
        l0 = l0 * al0 + ls0;
        l1 = l1 * al1 + ls1;
#pragma unroll
        for (int nb = 0; nb < 8; nb++) {
            Oacc[nb][0] *= al0; Oacc[nb][1] *= al0;
            Oacc[nb][2] *= al1; Oacc[nb][3] *= al1;
        }

        // ---- O += P @ V (3-term split) ----
#pragma unroll
        for (int kb = 0; kb < 4; kb++) {
            uint32_t ph[4], pl[4];
            split_pack2(sacc[2 * kb][0],     sacc[2 * kb][1],     ph[0], pl[0]);
            split_pack2(sacc[2 * kb][2],     sacc[2 * kb][3],     ph[1], pl[1]);
            split_pack2(sacc[2 * kb + 1][0], sacc[2 * kb + 1][1], ph[2], pl[2]);
            split_pack2(sacc[2 * kb + 1][2], sacc[2 * kb + 1][3], ph[3], pl[3]);
#pragma unroll
            for (int nbp = 0; nbp < 4; nbp++) {
                uint32_t vd = st + 2 * AT_T + (kb * 16 + v_row) * AT_ROWB + nbp * 32 + v_off;
                uint32_t rh[4], rl[4];
                ldsm4t(rh[0], rh[1], rh[2], rh[3], vd);
                ldsm4t(rl[0], rl[1], rl[2], rl[3], vd + AT_T);
                uint32_t v0h[2] = {rh[0], rh[1]}, v1h[2] = {rh[2], rh[3]};
                uint32_t v0l[2] = {rl[0], rl[1]}, v1l[2] = {rl[2], rl[3]};
                MMA16816(Oacc[2 * nbp],     ph, v0h);
                MMA16816(Oacc[2 * nbp],     pl, v0h);
                MMA16816(Oacc[2 * nbp],     ph, v0l);
                MMA16816(Oacc[2 * nbp + 1], ph, v1h);
                MMA16816(Oacc[2 * nbp + 1], pl, v1h);
                MMA16816(Oacc[2 * nbp + 1], ph, v1l);
            }
        }

        CP_WAIT0();
        __syncthreads();
    }

    // ---- finalize ----
    l0 += __shfl_xor_sync(0xffffffffu, l0, 1);
    l0 += __shfl_xor_sync(0xffffffffu, l0, 2);
    l1 += __shfl_xor_sync(0xffffffffu, l1, 1);
    l1 += __shfl_xor_sync(0xffffffffu, l1, 2);
    const float inv0 = 1.f / l0, inv1 = 1.f / l1;

    float* yb = y + ((size_t)b * T_ + q0 + wq) * C_ + h * D_;
#pragma unroll
    for (int nb = 0; nb < 8; nb++) {
        int col = nb * 8 + 2 * gc;
        *(float2*)(yb + (size_t)gr * C_ + col) =
            make_float2(Oacc[nb][0] * inv0, Oacc[nb][1] * inv0);
        *(float2*)(yb + (size_t)(gr + 8) * C_ + col) =
            make_float2(Oacc[nb][2] * inv1, Oacc[nb][3] * inv1);
    }
}

// ---------------- residual add + LayerNorm (+ optional split) --------------
template <bool SPLIT>
__global__ void __launch_bounds__(256) add_ln_kernel(
    const float* __restrict__ a, const float* __restrict__ bres,
    const float* __restrict__ g, const float* __restrict__ beta,
    float* __restrict__ out, __nv_bfloat16* __restrict__ Oh,
    __nv_bfloat16* __restrict__ Ol)
{
    const int row = blockIdx.x;
    const int tid = threadIdx.x;

    const float4 av = ((const float4*)(a    + (size_t)row * C_))[tid];
    const float4 bv = ((const float4*)(bres + (size_t)row * C_))[tid];
    float4 v = make_float4(av.x + bv.x, av.y + bv.y, av.z + bv.z, av.w + bv.w);

    float s  = v.x + v.y + v.z + v.w;
    float sq = v.x * v.x + v.y * v.y + v.z * v.z + v.w * v.w;
#pragma unroll
    for (int off = 16; off; off >>= 1) {
        s  += __shfl_xor_sync(0xffffffffu, s,  off);
        sq += __shfl_xor_sync(0xffffffffu, sq, off);
    }
    __shared__ float ws[8], wsq[8];
    if ((tid & 31) == 0) { ws[tid >> 5] = s; wsq[tid >> 5] = sq; }
    __syncthreads();
    float tot = 0.f, totq = 0.f;
#pragma unroll
    for (int i = 0; i < 8; i++) { tot += ws[i]; totq += wsq[i]; }

    const float mu   = tot * (1.0f / C_);
    const float var  = totq * (1.0f / C_) - mu * mu;
    const float rstd = rsqrtf(var + LN_EPS);

    const float4 gv = ((const float4*)g)[tid];
    const float4 be = ((const float4*)beta)[tid];
    float4 o;
    o.x = (v.x - mu) * rstd * gv.x + be.x;
    o.y = (v.y - mu) * rstd * gv.y + be.y;
    o.z = (v.z - mu) * rstd * gv.z + be.z;
    o.w = (v.w - mu) * rstd * gv.w + be.w;
    ((float4*)(out + (size_t)row * C_))[tid] = o;
    if (SPLIT) {
        uint32_t h0, l0v, h1, l1v;
        split_pack2(o.x, o.y, h0, l0v);
        split_pack2(o.z, o.w, h1, l1v);
        uint32_t* oh = (uint32_t*)(Oh + (size_t)row * C_);
        uint32_t* ol = (uint32_t*)(Ol + (size_t)row * C_);
        oh[2 * tid] = h0; oh[2 * tid + 1] = h1;
        ol[2 * tid] = l0v; ol[2 * tid + 1] = l1v;
    }
}

// ---------------- launcher --------------------------------------------------
extern "C" void kernel_launch(void* const* d_in, const int* in_sizes, int n_in,
                              void* d_out, int out_size)
{
    const float* x     = (const float*)d_in[0];
    const float* w_qkv = (const float*)d_in[1];
    const float* b_qkv = (const float*)d_in[2];
    const float* ln1_g = (const float*)d_in[3];
    const float* ln1_b = (const float*)d_in[4];
    const float* w_fc1 = (const float*)d_in[5];
    const float* b_fc1 = (const float*)d_in[6];
    const float* w_fc2 = (const float*)d_in[7];
    const float* b_fc2 = (const float*)d_in[8];
    const float* ln2_g = (const float*)d_in[9];
    const float* ln2_b = (const float*)d_in[10];
    float* out = (float*)d_out;

    float *att, *x1, *mlp;
    __nv_bfloat16 *qkvh, *qkvl, *ah, *al, *ah2, *al2, *bh, *bl;
    cudaGetSymbolAddress((void**)&att,  g_att);
    cudaGetSymbolAddress((void**)&x1,   g_x1);
    cudaGetSymbolAddress((void**)&mlp,  g_mlp);
    cudaGetSymbolAddress((void**)&qkvh, g_qkvh);
    cudaGetSymbolAddress((void**)&qkvl, g_qkvl);
    cudaGetSymbolAddress((void**)&ah,   g_ah);
    cudaGetSymbolAddress((void**)&al,   g_al);
    cudaGetSymbolAddress((void**)&ah2,  g_ah2);
    cudaGetSymbolAddress((void**)&al2,  g_al2);
    cudaGetSymbolAddress((void**)&bh,   g_bh);
    cudaGetSymbolAddress((void**)&bl,   g_bl);

    cudaFuncSetAttribute(gemm_mma<0>, cudaFuncAttributeMaxDynamicSharedMemorySize, GM_SMEM);
    cudaFuncSetAttribute(gemm_mma<1>, cudaFuncAttributeMaxDynamicSharedMemorySize, GM_SMEM);
    cudaFuncSetAttribute(gemm_mma<2>, cudaFuncAttributeMaxDynamicSharedMemorySize, GM_SMEM);
    cudaFuncSetAttribute(attn_tc, cudaFuncAttributeMaxDynamicSharedMemorySize, AT_SMEM);

    // ---- QKV = x @ w_qkv + b  -> split bf16 (Q scaled 1/8) ----
    split_act<<<(M_ * C_ / 4 + 255) / 256, 256>>>(x, ah, al, (size_t)M_ * C_ / 4);
    split_w_t<<<dim3(3 * C_ / 32, C_ / 32), dim3(32, 8)>>>(w_qkv, bh, bl, C_, 3 * C_);
    gemm_mma<1><<<dim3(3 * C_ / 128, M_ / 128), 256, GM_SMEM>>>(
        ah, al, bh, bl, b_qkv, nullptr, qkvh, qkvl, 3 * C_, C_);

    // ---- attention (tensor core) ----
    attn_tc<<<dim3(T_ / 64, H_, B_), 128, AT_SMEM>>>(qkvh, qkvl, att);

    // ---- x1 = LN1(x + att), fused split for FC1 A ----
    add_ln_kernel<true><<<M_, 256>>>(x, att, ln1_g, ln1_b, x1, ah, al);

    // ---- h = gelu(x1 @ w_fc1 + b) -> split bf16 ----
    split_w_t<<<dim3(4 * C_ / 32, C_ / 32), dim3(32, 8)>>>(w_fc1, bh, bl, C_, 4 * C_);
    gemm_mma<2><<<dim3(4 * C_ / 128, M_ / 128), 256, GM_SMEM>>>(
        ah, al, bh, bl, b_fc1, nullptr, ah2, al2, 4 * C_, C_);

    // ---- mlp = h @ w_fc2 + b (fp32) ----
    split_w_t<<<dim3(C_ / 32, 4 * C_ / 32), dim3(32, 8)>>>(w_fc2, bh, bl, 4 * C_, C_);
    gemm_mma<0><<<dim3(C_ / 128, M_ / 128), 256, GM_SMEM>>>(
        ah2, al2, bh, bl, b_fc2, mlp, nullptr, nullptr, C_, 4 * C_);

    // ---- out = LN2(x1 + mlp) ----
    add_ln_kernel<false><<<M_, 256>>>(x1, mlp, ln2_g, ln2_b, out, nullptr, nullptr);
}

// round 6
// speedup vs baseline: 2.9472x; 1.1086x over previous
#include <cuda_runtime.h>
#include <cuda_bf16.h>
#include <math.h>
#include <stdint.h>

#define B_   4
#define T_   2048
#define C_   1024
#define H_   16
#define D_   64
#define M_   (B_ * T_)           // 8192 rows
#define LN_EPS 1e-5f

// ---------------- scratch (static device globals; no allocation) -----------
__device__ __align__(128) float g_att[(size_t)M_ * C_];
__device__ __align__(128) float g_x1 [(size_t)M_ * C_];
__device__ __align__(128) float g_mlp[(size_t)M_ * C_];
__device__ __align__(128) __nv_bfloat16 g_qkvh[(size_t)M_ * 3 * C_];
__device__ __align__(128) __nv_bfloat16 g_qkvl[(size_t)M_ * 3 * C_];
__device__ __align__(128) __nv_bfloat16 g_ah [(size_t)M_ * C_];       // A hi (x / x1)
__device__ __align__(128) __nv_bfloat16 g_al [(size_t)M_ * C_];
__device__ __align__(128) __nv_bfloat16 g_ah2[(size_t)M_ * 4 * C_];   // gelu(h) hi
__device__ __align__(128) __nv_bfloat16 g_al2[(size_t)M_ * 4 * C_];
__device__ __align__(128) __nv_bfloat16 g_bh [(size_t)4 * C_ * C_];   // B hi [N,K]
__device__ __align__(128) __nv_bfloat16 g_bl [(size_t)4 * C_ * C_];

__device__ __forceinline__ float gelu_exact(float x) {
    return 0.5f * x * (1.0f + erff(x * 0.70710678118654752440f));
}

// ---------------- PTX helpers ----------------------------------------------
__device__ __forceinline__ uint32_t smem_u32(const void* p) {
    uint32_t a;
    asm("{ .reg .u64 t; cvta.to.shared.u64 t, %1; cvt.u32.u64 %0, t; }" : "=r"(a) : "l"(p));
    return a;
}
#define CP16(s, g) asm volatile("cp.async.cg.shared.global [%0], [%1], 16;" :: "r"(s), "l"(g))
#define CP_COMMIT() asm volatile("cp.async.commit_group;" ::: "memory")
#define CP_WAIT1()  asm volatile("cp.async.wait_group 1;" ::: "memory")
#define CP_WAIT0()  asm volatile("cp.async.wait_group 0;" ::: "memory")

__device__ __forceinline__ void ldsm4(uint32_t& r0, uint32_t& r1,
                                      uint32_t& r2, uint32_t& r3, uint32_t addr) {
    asm volatile("ldmatrix.sync.aligned.m8n8.x4.shared.b16 {%0,%1,%2,%3}, [%4];"
                 : "=r"(r0), "=r"(r1), "=r"(r2), "=r"(r3) : "r"(addr));
}
__device__ __forceinline__ void ldsm4t(uint32_t& r0, uint32_t& r1,
                                       uint32_t& r2, uint32_t& r3, uint32_t addr) {
    asm volatile("ldmatrix.sync.aligned.m8n8.x4.trans.shared.b16 {%0,%1,%2,%3}, [%4];"
                 : "=r"(r0), "=r"(r1), "=r"(r2), "=r"(r3) : "r"(addr));
}
#define MMA16816(c, a, b)                                                     \
    asm volatile("mma.sync.aligned.m16n8k16.row.col.f32.bf16.bf16.f32 "       \
                 "{%0,%1,%2,%3}, {%4,%5,%6,%7}, {%8,%9}, {%0,%1,%2,%3};"      \
                 : "+f"((c)[0]), "+f"((c)[1]), "+f"((c)[2]), "+f"((c)[3])     \
                 : "r"((a)[0]), "r"((a)[1]), "r"((a)[2]), "r"((a)[3]),        \
                   "r"((b)[0]), "r"((b)[1]))

__device__ __forceinline__ uint32_t pack_bf16x2(float lo, float hi) {
    uint32_t r;
    asm("cvt.rn.bf16x2.f32 %0, %1, %2;" : "=r"(r) : "f"(hi), "f"(lo));
    return r;
}
__device__ __forceinline__ void split_pack2(float x, float y, uint32_t& hi, uint32_t& lo) {
    float hx = __bfloat162float(__float2bfloat16(x));
    float hy = __bfloat162float(__float2bfloat16(y));
    hi = pack_bf16x2(hx, hy);
    lo = pack_bf16x2(x - hx, y - hy);
}

// ---------------- split kernels --------------------------------------------
__global__ void __launch_bounds__(256) split_act(
    const float* __restrict__ X, __nv_bfloat16* __restrict__ Hh,
    __nv_bfloat16* __restrict__ Ll, size_t n4)
{
    size_t i = (size_t)blockIdx.x * blockDim.x + threadIdx.x;
    if (i >= n4) return;
    float4 v = ((const float4*)X)[i];
    uint32_t h0, l0, h1, l1;
    split_pack2(v.x, v.y, h0, l0);
    split_pack2(v.z, v.w, h1, l1);
    ((uint32_t*)Hh)[2 * i] = h0; ((uint32_t*)Hh)[2 * i + 1] = h1;
    ((uint32_t*)Ll)[2 * i] = l0; ((uint32_t*)Ll)[2 * i + 1] = l1;
}

// W [K,N] fp32 -> Bh/Bl [N,K] bf16 (transpose + split)
__global__ void __launch_bounds__(256) split_w_t(
    const float* __restrict__ W, __nv_bfloat16* __restrict__ Bh,
    __nv_bfloat16* __restrict__ Bl, int K, int N)
{
    __shared__ float t[32][33];
    const int tx = threadIdx.x, ty = threadIdx.y;   // block (32,8)
    const int n0 = blockIdx.x * 32, k0 = blockIdx.y * 32;
#pragma unroll
    for (int r = 0; r < 4; r++)
        t[ty + r * 8][tx] = W[(size_t)(k0 + ty + r * 8) * N + n0 + tx];
    __syncthreads();
#pragma unroll
    for (int r = 0; r < 4; r++) {
        int nn = ty + r * 8;
        float v = t[tx][nn];
        __nv_bfloat16 h = __float2bfloat16(v);
        __nv_bfloat16 l = __float2bfloat16(v - __bfloat162float(h));
        size_t o = (size_t)(n0 + nn) * K + k0 + tx;
        Bh[o] = h; Bl[o] = l;
    }
}

// ---------------- HMMA split-bf16 GEMM --------------------------------------
// C = Ah@Bh^T + Al@Bh^T + Ah@Bl^T + bias  (fp32 accum)
// CTA tile 256x128, warp tile 64x64 (8 warps = 4m x 2n), BK=32, 3 stages.
// MODE 0: fp32 out; MODE 1: split bf16 out, cols<C_ scaled 0.125 (QKV);
// MODE 2: gelu then split bf16 out.
#define GM_BK    32
#define GM_ROWB  80
#define GM_AOP   (256 * GM_ROWB)              // 20480
#define GM_BOP   (128 * GM_ROWB)              // 10240
#define GM_STAGE (2 * GM_AOP + 2 * GM_BOP)    // 61440
#define GM_SMEM  (3 * GM_STAGE)               // 184320

template <int MODE>
__global__ void __launch_bounds__(256, 1) gemm_mma(
    const __nv_bfloat16* __restrict__ Ah, const __nv_bfloat16* __restrict__ Al,
    const __nv_bfloat16* __restrict__ Bh, const __nv_bfloat16* __restrict__ Bl,
    const float* __restrict__ bias, float* __restrict__ Cmat,
    __nv_bfloat16* __restrict__ Oh, __nv_bfloat16* __restrict__ Ol,
    int N, int K)
{
    extern __shared__ char smem[];
    const uint32_t sb = smem_u32(smem);
    const int tid  = threadIdx.x;
    const int lane = tid & 31;
    const int wid  = tid >> 5;
    const int m0 = blockIdx.y * 256;
    const int n0 = blockIdx.x * 128;
    const int wm = (wid >> 1) * 64;
    const int wn = (wid & 1) * 64;

    const int nch = K / GM_BK;

    auto load_chunk = [&](int c) {
        const int kk = c * GM_BK;
        const uint32_t st = sb + (c % 3) * GM_STAGE;
#pragma unroll
        for (int i = 0; i < 4; i++) {                // A: 1024 units x2 ops
            int u = tid + i * 256;
            int r = u >> 2, cc = u & 3;
            uint32_t so = r * GM_ROWB + cc * 16;
            size_t ga = (size_t)(m0 + r) * K + kk + cc * 8;
            CP16(st + so,           Ah + ga);
            CP16(st + GM_AOP + so,  Al + ga);
        }
#pragma unroll
        for (int i = 0; i < 2; i++) {                // B: 512 units x2 ops
            int u = tid + i * 256;
            int r = u >> 2, cc = u & 3;
            uint32_t so = r * GM_ROWB + cc * 16;
            size_t gb = (size_t)(n0 + r) * K + kk + cc * 8;
            CP16(st + 2 * GM_AOP + so,          Bh + gb);
            CP16(st + 2 * GM_AOP + GM_BOP + so, Bl + gb);
        }
    };

    float acc[4][8][4];
#pragma unroll
    for (int i = 0; i < 4; i++)
#pragma unroll
        for (int j = 0; j < 8; j++)
#pragma unroll
            for (int t = 0; t < 4; t++) acc[i][j][t] = 0.f;

    load_chunk(0); CP_COMMIT();
    load_chunk(1); CP_COMMIT();

    const int a_row = lane & 15;
    const int a_off = (lane >> 4) * 16;
    const int b_row = (lane & 7) + ((lane >> 4) << 3);
    const int b_off = ((lane >> 3) & 1) * 16;

    for (int k = 0; k < nch; k++) {
        CP_WAIT1();
        __syncthreads();
        if (k + 2 < nch) { load_chunk(k + 2); CP_COMMIT(); }

        const uint32_t stA = sb + (k % 3) * GM_STAGE;
        const uint32_t stB = stA + 2 * GM_AOP;

#pragma unroll
        for (int ks = 0; ks < 2; ks++) {
            uint32_t ah[4][4], al[4][4];
#pragma unroll
            for (int mb = 0; mb < 4; mb++) {
                uint32_t ad = stA + (wm + mb * 16 + a_row) * GM_ROWB + ks * 32 + a_off;
                ldsm4(ah[mb][0], ah[mb][1], ah[mb][2], ah[mb][3], ad);
                ldsm4(al[mb][0], al[mb][1], al[mb][2], al[mb][3], ad + GM_AOP);
            }
#pragma unroll
            for (int nbp = 0; nbp < 4; nbp++) {
                uint32_t bd = stB + (wn + nbp * 16 + b_row) * GM_ROWB + ks * 32 + b_off;
                uint32_t h0, h1, h2, h3, q0, q1, q2, q3;
                ldsm4(h0, h1, h2, h3, bd);
                ldsm4(q0, q1, q2, q3, bd + GM_BOP);
                uint32_t b0h[2] = {h0, h1}, b1h[2] = {h2, h3};
                uint32_t b0l[2] = {q0, q1}, b1l[2] = {q2, q3};
#pragma unroll
                for (int mb = 0; mb < 4; mb++) {
                    MMA16816(acc[mb][2 * nbp],     ah[mb], b0h);
                    MMA16816(acc[mb][2 * nbp],     al[mb], b0h);
                    MMA16816(acc[mb][2 * nbp],     ah[mb], b0l);
                    MMA16816(acc[mb][2 * nbp + 1], ah[mb], b1h);
                    MMA16816(acc[mb][2 * nbp + 1], al[mb], b1h);
                    MMA16816(acc[mb][2 * nbp + 1], ah[mb], b1l);
                }
            }
        }
    }

    // ---- epilogue ----
    const int gr = lane >> 2;
    const int gc = (lane & 3) * 2;
#pragma unroll
    for (int mb = 0; mb < 4; mb++) {
#pragma unroll
        for (int nb = 0; nb < 8; nb++) {
            int row = m0 + wm + mb * 16 + gr;
            int col = n0 + wn + nb * 8 + gc;
            float b0 = __ldg(&bias[col]), b1 = __ldg(&bias[col + 1]);
            float v0 = acc[mb][nb][0] + b0, v1 = acc[mb][nb][1] + b1;
            float v2 = acc[mb][nb][2] + b0, v3 = acc[mb][nb][3] + b1;
            if (MODE == 0) {
                *(float2*)(Cmat + (size_t)row * N + col)       = make_float2(v0, v1);
                *(float2*)(Cmat + (size_t)(row + 8) * N + col) = make_float2(v2, v3);
            } else {
                if (MODE == 1 && col < C_) { v0 *= 0.125f; v1 *= 0.125f; v2 *= 0.125f; v3 *= 0.125f; }
                if (MODE == 2) {
                    v0 = gelu_exact(v0); v1 = gelu_exact(v1);
                    v2 = gelu_exact(v2); v3 = gelu_exact(v3);
                }
                uint32_t h01, l01, h23, l23;
                split_pack2(v0, v1, h01, l01);
                split_pack2(v2, v3, h23, l23);
                *(uint32_t*)(Oh + (size_t)row * N + col)       = h01;
                *(uint32_t*)(Ol + (size_t)row * N + col)       = l01;
                *(uint32_t*)(Oh + (size_t)(row + 8) * N + col) = h23;
                *(uint32_t*)(Ol + (size_t)(row + 8) * N + col) = l23;
            }
        }
    }
}

// ---------------- tensor-core causal flash attention ------------------------
// 128 queries per CTA (8 warps x 16 rows), 64-key tiles, split-bf16 MMAs.
#define AT_ROWB  144
#define AQ_T     (128 * AT_ROWB)             // 18432 per Q operand
#define AK_T     (64 * AT_ROWB)              // 9216 per K/V operand
#define AT_STAGE (4 * AK_T)                  // Kh,Kl,Vh,Vl = 36864
#define AT_SMEM  (2 * AQ_T + 2 * AT_STAGE)   // 110592

__global__ void __launch_bounds__(256, 1) attn_tc(
    const __nv_bfloat16* __restrict__ qkvh,
    const __nv_bfloat16* __restrict__ qkvl,
    float* __restrict__ y)
{
    extern __shared__ char smem[];
    const uint32_t sb = smem_u32(smem);
    const int tid = threadIdx.x, lane = tid & 31, wid = tid >> 5;
    const int qb = (int)gridDim.x - 1 - (int)blockIdx.x;   // big blocks first
    const int h = blockIdx.y, b = blockIdx.z;
    const int q0 = qb * 128;
    const int wq = wid * 16;
    const int gr = lane >> 2, gc = lane & 3;
    const int RS = 3 * C_;

    const __nv_bfloat16* qh = qkvh + (size_t)b * T_ * RS + h * D_;
    const __nv_bfloat16* ql = qkvl + (size_t)b * T_ * RS + h * D_;
    const __nv_bfloat16* kh = qh + C_;
    const __nv_bfloat16* kl = ql + C_;
    const __nv_bfloat16* vh = qh + 2 * C_;
    const __nv_bfloat16* vl = ql + 2 * C_;

    const uint32_t QH  = sb;
    const uint32_t ST0 = sb + 2 * AQ_T;

    // load Q (hi/lo) tile: 128 rows x 128B each
#pragma unroll
    for (int t = 0; t < 2; t++) {
        const __nv_bfloat16* g = t ? ql : qh;
#pragma unroll
        for (int i = 0; i < 4; i++) {
            int u = tid + i * 256;          // 0..1023
            int r = u >> 3, c = u & 7;
            CP16(QH + t * AQ_T + r * AT_ROWB + c * 16, g + (size_t)(q0 + r) * RS + c * 8);
        }
    }

    auto load_tile = [&](int kt, int bufsel) {
        uint32_t st = ST0 + bufsel * AT_STAGE;
#pragma unroll
        for (int t = 0; t < 4; t++) {
            const __nv_bfloat16* g = (t == 0 ? kh : t == 1 ? kl : t == 2 ? vh : vl);
#pragma unroll
            for (int i = 0; i < 2; i++) {
                int u = tid + i * 256;      // 0..511
                int r = u >> 3, c = u & 7;
                CP16(st + t * AK_T + r * AT_ROWB + c * 16, g + (size_t)(kt * 64 + r) * RS + c * 8);
            }
        }
    };
    load_tile(0, 0);
    CP_COMMIT();
    CP_WAIT0();
    __syncthreads();

    // Q fragments
    uint32_t qfh[4][4], qfl[4][4];
    const int a_row = lane & 15, a_off = (lane >> 4) * 16;
#pragma unroll
    for (int ks = 0; ks < 4; ks++) {
        uint32_t ad = QH + (wq + a_row) * AT_ROWB + ks * 32 + a_off;
        ldsm4(qfh[ks][0], qfh[ks][1], qfh[ks][2], qfh[ks][3], ad);
        ldsm4(qfl[ks][0], qfl[ks][1], qfl[ks][2], qfl[ks][3], ad + AQ_T);
    }

    float Oacc[8][4];
#pragma unroll
    for (int i = 0; i < 8; i++)
#pragma unroll
        for (int j = 0; j < 4; j++) Oacc[i][j] = 0.f;
    float m0 = -1e30f, m1 = -1e30f, l0 = 0.f, l1 = 0.f;

    const int nt = 2 * qb + 2;
    const int b_row = (lane & 7) + ((lane >> 4) << 3);
    const int b_off = ((lane >> 3) & 1) * 16;
    const int v_row = (lane & 7) + ((lane >> 3) & 1) * 8;
    const int v_off = (lane >> 4) * 16;

    for (int kt = 0; kt < nt; kt++) {
        if (kt + 1 < nt) { load_tile(kt + 1, (kt + 1) & 1); CP_COMMIT(); }
        const uint32_t st = ST0 + (kt & 1) * AT_STAGE;

        // warp-level skip: keys all strictly above this warp's queries
        const bool active = (kt * 64) <= (q0 + wq + 15);
        if (active) {
            // ---- S = Q @ K^T (3-term split) ----
            float sacc[8][4];
#pragma unroll
            for (int i = 0; i < 8; i++)
#pragma unroll
                for (int j = 0; j < 4; j++) sacc[i][j] = 0.f;

#pragma unroll
            for (int nbp = 0; nbp < 4; nbp++) {
#pragma unroll
                for (int ks = 0; ks < 4; ks++) {
                    uint32_t kd = st + (nbp * 16 + b_row) * AT_ROWB + ks * 32 + b_off;
                    uint32_t rh[4], rl[4];
                    ldsm4(rh[0], rh[1], rh[2], rh[3], kd);
                    ldsm4(rl[0], rl[1], rl[2], rl[3], kd + AK_T);
                    uint32_t b0h[2] = {rh[0], rh[1]}, b1h[2] = {rh[2], rh[3]};
                    uint32_t b0l[2] = {rl[0], rl[1]}, b1l[2] = {rl[2], rl[3]};
                    MMA16816(sacc[2 * nbp],     qfh[ks], b0h);
                    MMA16816(sacc[2 * nbp],     qfl[ks], b0h);
                    MMA16816(sacc[2 * nbp],     qfh[ks], b0l);
                    MMA16816(sacc[2 * nbp + 1], qfh[ks], b1h);
                    MMA16816(sacc[2 * nbp + 1], qfl[ks], b1h);
                    MMA16816(sacc[2 * nbp + 1], qfh[ks], b1l);
                }
            }

            // ---- causal mask (only when tile crosses the diagonal) ----
            if (kt * 64 + 63 > q0 + wq) {
                const int qg0 = q0 + wq + gr, qg1 = qg0 + 8;
#pragma unroll
                for (int nb = 0; nb < 8; nb++) {
                    int kg = kt * 64 + nb * 8 + 2 * gc;
                    if (kg     > qg0) sacc[nb][0] = -1e30f;
                    if (kg + 1 > qg0) sacc[nb][1] = -1e30f;
                    if (kg     > qg1) sacc[nb][2] = -1e30f;
                    if (kg + 1 > qg1) sacc[nb][3] = -1e30f;
                }
            }

            // ---- online softmax ----
            float mx0 = m0, mx1 = m1;
#pragma unroll
            for (int nb = 0; nb < 8; nb++) {
                mx0 = fmaxf(mx0, fmaxf(sacc[nb][0], sacc[nb][1]));
                mx1 = fmaxf(mx1, fmaxf(sacc[nb][2], sacc[nb][3]));
            }
            mx0 = fmaxf(mx0, __shfl_xor_sync(0xffffffffu, mx0, 1));
            mx0 = fmaxf(mx0, __shfl_xor_sync(0xffffffffu, mx0, 2));
            mx1 = fmaxf(mx1, __shfl_xor_sync(0xffffffffu, mx1, 1));
            mx1 = fmaxf(mx1, __shfl_xor_sync(0xffffffffu, mx1, 2));
            float al0 = __expf(m0 - mx0), al1 = __expf(m1 - mx1);
            m0 = mx0; m1 = mx1;
            float ls0 = 0.f, ls1 = 0.f;
#pragma unroll
            for (int nb = 0; nb < 8; nb++) {
                sacc[nb][0] = __expf(sacc[nb][0] - mx0); ls0 += sacc[nb][0];
                sacc[nb][1] = __expf(sacc[nb][1] - mx0); ls0 += sacc[nb][1];
                sacc[nb][2] = __expf(sacc[nb][2] - mx1); ls1 += sacc[nb][2];
                sacc[nb][3] = __expf(sacc[nb][3] - mx1); ls1 += sacc[nb][3];
            }
            l0 = l0 * al0 + ls0;
            l1 = l1 * al1 + ls1;
#pragma unroll
            for (int nb = 0; nb < 8; nb++) {
                Oacc[nb][0] *= al0; Oacc[nb][1] *= al0;
                Oacc[nb][2] *= al1; Oacc[nb][3] *= al1;
            }

            // ---- O += P @ V (3-term split) ----
#pragma unroll
            for (int kb = 0; kb < 4; kb++) {
                uint32_t ph[4], pl[4];
                split_pack2(sacc[2 * kb][0],     sacc[2 * kb][1],     ph[0], pl[0]);
                split_pack2(sacc[2 * kb][2],     sacc[2 * kb][3],     ph[1], pl[1]);
                split_pack2(sacc[2 * kb + 1][0], sacc[2 * kb + 1][1], ph[2], pl[2]);
                split_pack2(sacc[2 * kb + 1][2], sacc[2 * kb + 1][3], ph[3], pl[3]);
#pragma unroll
                for (int nbp = 0; nbp < 4; nbp++) {
                    uint32_t vd = st + 2 * AK_T + (kb * 16 + v_row) * AT_ROWB + nbp * 32 + v_off;
                    uint32_t rh[4], rl[4];
                    ldsm4t(rh[0], rh[1], rh[2], rh[3], vd);
                    ldsm4t(rl[0], rl[1], rl[2], rl[3], vd + AK_T);
                    uint32_t v0h[2] = {rh[0], rh[1]}, v1h[2] = {rh[2], rh[3]};
                    uint32_t v0l[2] = {rl[0], rl[1]}, v1l[2] = {rl[2], rl[3]};
                    MMA16816(Oacc[2 * nbp],     ph, v0h);
                    MMA16816(Oacc[2 * nbp],     pl, v0h);
                    MMA16816(Oacc[2 * nbp],     ph, v0l);
                    MMA16816(Oacc[2 * nbp + 1], ph, v1h);
                    MMA16816(Oacc[2 * nbp + 1], pl, v1h);
                    MMA16816(Oacc[2 * nbp + 1], ph, v1l);
                }
            }
        }

        CP_WAIT0();
        __syncthreads();
    }

    // ---- finalize ----
    l0 += __shfl_xor_sync(0xffffffffu, l0, 1);
    l0 += __shfl_xor_sync(0xffffffffu, l0, 2);
    l1 += __shfl_xor_sync(0xffffffffu, l1, 1);
    l1 += __shfl_xor_sync(0xffffffffu, l1, 2);
    const float inv0 = 1.f / l0, inv1 = 1.f / l1;

    float* yb = y + ((size_t)b * T_ + q0 + wq) * C_ + h * D_;
#pragma unroll
    for (int nb = 0; nb < 8; nb++) {
        int col = nb * 8 + 2 * gc;
        *(float2*)(yb + (size_t)gr * C_ + col) =
            make_float2(Oacc[nb][0] * inv0, Oacc[nb][1] * inv0);
        *(float2*)(yb + (size_t)(gr + 8) * C_ + col) =
            make_float2(Oacc[nb][2] * inv1, Oacc[nb][3] * inv1);
    }
}

// ---------------- residual add + LayerNorm (+ optional split) --------------
template <bool SPLIT>
__global__ void __launch_bounds__(256) add_ln_kernel(
    const float* __restrict__ a, const float* __restrict__ bres,
    const float* __restrict__ g, const float* __restrict__ beta,
    float* __restrict__ out, __nv_bfloat16* __restrict__ Oh,
    __nv_bfloat16* __restrict__ Ol)
{
    const int row = blockIdx.x;
    const int tid = threadIdx.x;

    const float4 av = ((const float4*)(a    + (size_t)row * C_))[tid];
    const float4 bv = ((const float4*)(bres + (size_t)row * C_))[tid];
    float4 v = make_float4(av.x + bv.x, av.y + bv.y, av.z + bv.z, av.w + bv.w);

    float s  = v.x + v.y + v.z + v.w;
    float sq = v.x * v.x + v.y * v.y + v.z * v.z + v.w * v.w;
#pragma unroll
    for (int off = 16; off; off >>= 1) {
        s  += __shfl_xor_sync(0xffffffffu, s,  off);
        sq += __shfl_xor_sync(0xffffffffu, sq, off);
    }
    __shared__ float ws[8], wsq[8];
    if ((tid & 31) == 0) { ws[tid >> 5] = s; wsq[tid >> 5] = sq; }
    __syncthreads();
    float tot = 0.f, totq = 0.f;
#pragma unroll
    for (int i = 0; i < 8; i++) { tot += ws[i]; totq += wsq[i]; }

    const float mu   = tot * (1.0f / C_);
    const float var  = totq * (1.0f / C_) - mu * mu;
    const float rstd = rsqrtf(var + LN_EPS);

    const float4 gv = ((const float4*)g)[tid];
    const float4 be = ((const float4*)beta)[tid];
    float4 o;
    o.x = (v.x - mu) * rstd * gv.x + be.x;
    o.y = (v.y - mu) * rstd * gv.y + be.y;
    o.z = (v.z - mu) * rstd * gv.z + be.z;
    o.w = (v.w - mu) * rstd * gv.w + be.w;
    ((float4*)(out + (size_t)row * C_))[tid] = o;
    if (SPLIT) {
        uint32_t h0, l0v, h1, l1v;
        split_pack2(o.x, o.y, h0, l0v);
        split_pack2(o.z, o.w, h1, l1v);
        uint32_t* oh = (uint32_t*)(Oh + (size_t)row * C_);
        uint32_t* ol = (uint32_t*)(Ol + (size_t)row * C_);
        oh[2 * tid] = h0; oh[2 * tid + 1] = h1;
        ol[2 * tid] = l0v; ol[2 * tid + 1] = l1v;
    }
}

// ---------------- launcher --------------------------------------------------
extern "C" void kernel_launch(void* const* d_in, const int* in_sizes, int n_in,
                              void* d_out, int out_size)
{
    const float* x     = (const float*)d_in[0];
    const float* w_qkv = (const float*)d_in[1];
    const float* b_qkv = (const float*)d_in[2];
    const float* ln1_g = (const float*)d_in[3];
    const float* ln1_b = (const float*)d_in[4];
    const float* w_fc1 = (const float*)d_in[5];
    const float* b_fc1 = (const float*)d_in[6];
    const float* w_fc2 = (const float*)d_in[7];
    const float* b_fc2 = (const float*)d_in[8];
    const float* ln2_g = (const float*)d_in[9];
    const float* ln2_b = (const float*)d_in[10];
    float* out = (float*)d_out;

    float *att, *x1, *mlp;
    __nv_bfloat16 *qkvh, *qkvl, *ah, *al, *ah2, *al2, *bh, *bl;
    cudaGetSymbolAddress((void**)&att,  g_att);
    cudaGetSymbolAddress((void**)&x1,   g_x1);
    cudaGetSymbolAddress((void**)&mlp,  g_mlp);
    cudaGetSymbolAddress((void**)&qkvh, g_qkvh);
    cudaGetSymbolAddress((void**)&qkvl, g_qkvl);
    cudaGetSymbolAddress((void**)&ah,   g_ah);
    cudaGetSymbolAddress((void**)&al,   g_al);
    cudaGetSymbolAddress((void**)&ah2,  g_ah2);
    cudaGetSymbolAddress((void**)&al2,  g_al2);
    cudaGetSymbolAddress((void**)&bh,   g_bh);
    cudaGetSymbolAddress((void**)&bl,   g_bl);

    cudaFuncSetAttribute(gemm_mma<0>, cudaFuncAttributeMaxDynamicSharedMemorySize, GM_SMEM);
    cudaFuncSetAttribute(gemm_mma<1>, cudaFuncAttributeMaxDynamicSharedMemorySize, GM_SMEM);
    cudaFuncSetAttribute(gemm_mma<2>, cudaFuncAttributeMaxDynamicSharedMemorySize, GM_SMEM);
    cudaFuncSetAttribute(attn_tc, cudaFuncAttributeMaxDynamicSharedMemorySize, AT_SMEM);

    // ---- QKV = x @ w_qkv + b  -> split bf16 (Q scaled 1/8) ----
    split_act<<<(M_ * C_ / 4 + 255) / 256, 256>>>(x, ah, al, (size_t)M_ * C_ / 4);
    split_w_t<<<dim3(3 * C_ / 32, C_ / 32), dim3(32, 8)>>>(w_qkv, bh, bl, C_, 3 * C_);
    gemm_mma<1><<<dim3(3 * C_ / 128, M_ / 256), 256, GM_SMEM>>>(
        ah, al, bh, bl, b_qkv, nullptr, qkvh, qkvl, 3 * C_, C_);

    // ---- attention (tensor core, 128 q / CTA) ----
    attn_tc<<<dim3(T_ / 128, H_, B_), 256, AT_SMEM>>>(qkvh, qkvl, att);

    // ---- x1 = LN1(x + att), fused split for FC1 A ----
    add_ln_kernel<true><<<M_, 256>>>(x, att, ln1_g, ln1_b, x1, ah, al);

    // ---- h = gelu(x1 @ w_fc1 + b) -> split bf16 ----
    split_w_t<<<dim3(4 * C_ / 32, C_ / 32), dim3(32, 8)>>>(w_fc1, bh, bl, C_, 4 * C_);
    gemm_mma<2><<<dim3(4 * C_ / 128, M_ / 256), 256, GM_SMEM>>>(
        ah, al, bh, bl, b_fc1, nullptr, ah2, al2, 4 * C_, C_);

    // ---- mlp = h @ w_fc2 + b (fp32) ----
    split_w_t<<<dim3(C_ / 32, 4 * C_ / 32), dim3(32, 8)>>>(w_fc2, bh, bl, 4 * C_, C_);
    gemm_mma<0><<<dim3(C_ / 128, M_ / 256), 256, GM_SMEM>>>(
        ah2, al2, bh, bl, b_fc2, mlp, nullptr, nullptr, C_, 4 * C_);

    // ---- out = LN2(x1 + mlp) ----
    add_ln_kernel<false><<<M_, 256>>>(x1, mlp, ln2_g, ln2_b, out, nullptr, nullptr);
}

// round 7
// speedup vs baseline: 3.6863x; 1.2508x over previous
#include <cuda_runtime.h>
#include <cuda_fp16.h>
#include <math.h>
#include <stdint.h>

#define B_   4
#define T_   2048
#define C_   1024
#define H_   16
#define D_   64
#define M_   (B_ * T_)           // 8192 rows
#define LN_EPS 1e-5f

// ---------------- scratch (static device globals; no allocation) -----------
__device__ __align__(128) float g_att[(size_t)M_ * C_];
__device__ __align__(128) float g_x1 [(size_t)M_ * C_];
__device__ __align__(128) float g_mlp[(size_t)M_ * C_];
__device__ __align__(128) __half g_qkvh[(size_t)M_ * 3 * C_];
__device__ __align__(128) __half g_qkvl[(size_t)M_ * 3 * C_];
__device__ __align__(128) __half g_ah [(size_t)M_ * C_];       // A hi (x / x1)
__device__ __align__(128) __half g_al [(size_t)M_ * C_];
__device__ __align__(128) __half g_ah2[(size_t)M_ * 4 * C_];   // gelu(h) hi
__device__ __align__(128) __half g_al2[(size_t)M_ * 4 * C_];
__device__ __align__(128) __half g_bh [(size_t)4 * C_ * C_];   // B hi [N,K] (single-rounded)

__device__ __forceinline__ float gelu_exact(float x) {
    return 0.5f * x * (1.0f + erff(x * 0.70710678118654752440f));
}

// ---------------- PTX helpers ----------------------------------------------
__device__ __forceinline__ uint32_t smem_u32(const void* p) {
    uint32_t a;
    asm("{ .reg .u64 t; cvta.to.shared.u64 t, %1; cvt.u32.u64 %0, t; }" : "=r"(a) : "l"(p));
    return a;
}
#define CP16(s, g) asm volatile("cp.async.cg.shared.global [%0], [%1], 16;" :: "r"(s), "l"(g))
#define CP_COMMIT() asm volatile("cp.async.commit_group;" ::: "memory")
#define CP_WAIT1()  asm volatile("cp.async.wait_group 1;" ::: "memory")
#define CP_WAIT0()  asm volatile("cp.async.wait_group 0;" ::: "memory")

__device__ __forceinline__ void ldsm4(uint32_t& r0, uint32_t& r1,
                                      uint32_t& r2, uint32_t& r3, uint32_t addr) {
    asm volatile("ldmatrix.sync.aligned.m8n8.x4.shared.b16 {%0,%1,%2,%3}, [%4];"
                 : "=r"(r0), "=r"(r1), "=r"(r2), "=r"(r3) : "r"(addr));
}
__device__ __forceinline__ void ldsm4t(uint32_t& r0, uint32_t& r1,
                                       uint32_t& r2, uint32_t& r3, uint32_t addr) {
    asm volatile("ldmatrix.sync.aligned.m8n8.x4.trans.shared.b16 {%0,%1,%2,%3}, [%4];"
                 : "=r"(r0), "=r"(r1), "=r"(r2), "=r"(r3) : "r"(addr));
}
#define MMA16816(c, a, b)                                                     \
    asm volatile("mma.sync.aligned.m16n8k16.row.col.f32.f16.f16.f32 "         \
                 "{%0,%1,%2,%3}, {%4,%5,%6,%7}, {%8,%9}, {%0,%1,%2,%3};"      \
                 : "+f"((c)[0]), "+f"((c)[1]), "+f"((c)[2]), "+f"((c)[3])     \
                 : "r"((a)[0]), "r"((a)[1]), "r"((a)[2]), "r"((a)[3]),        \
                   "r"((b)[0]), "r"((b)[1]))

__device__ __forceinline__ uint32_t pack_f16x2(float lo, float hi) {
    uint32_t r;
    asm("cvt.rn.f16x2.f32 %0, %1, %2;" : "=r"(r) : "f"(hi), "f"(lo));
    return r;
}
// split (x,y) into hi f16x2 + residual-lo f16x2
__device__ __forceinline__ void split_pack2(float x, float y, uint32_t& hi, uint32_t& lo) {
    float hx = __half2float(__float2half_rn(x));
    float hy = __half2float(__float2half_rn(y));
    hi = pack_f16x2(hx, hy);
    lo = pack_f16x2(x - hx, y - hy);
}

// ---------------- split kernels --------------------------------------------
__global__ void __launch_bounds__(256) split_act(
    const float* __restrict__ X, __half* __restrict__ Hh,
    __half* __restrict__ Ll, size_t n4)
{
    size_t i = (size_t)blockIdx.x * blockDim.x + threadIdx.x;
    if (i >= n4) return;
    float4 v = ((const float4*)X)[i];
    uint32_t h0, l0, h1, l1;
    split_pack2(v.x, v.y, h0, l0);
    split_pack2(v.z, v.w, h1, l1);
    ((uint32_t*)Hh)[2 * i] = h0; ((uint32_t*)Hh)[2 * i + 1] = h1;
    ((uint32_t*)Ll)[2 * i] = l0; ((uint32_t*)Ll)[2 * i + 1] = l1;
}

// W [K,N] fp32 -> Bh [N,K] fp16 (transpose + single rounding)
__global__ void __launch_bounds__(256) round_w_t(
    const float* __restrict__ W, __half* __restrict__ Bh, int K, int N)
{
    __shared__ float t[32][33];
    const int tx = threadIdx.x, ty = threadIdx.y;   // block (32,8)
    const int n0 = blockIdx.x * 32, k0 = blockIdx.y * 32;
#pragma unroll
    for (int r = 0; r < 4; r++)
        t[ty + r * 8][tx] = W[(size_t)(k0 + ty + r * 8) * N + n0 + tx];
    __syncthreads();
#pragma unroll
    for (int r = 0; r < 4; r++) {
        int nn = ty + r * 8;
        Bh[(size_t)(n0 + nn) * K + k0 + tx] = __float2half_rn(t[tx][nn]);
    }
}

// ---------------- HMMA split-fp16 GEMM --------------------------------------
// C = Ah@Bh^T + Al@Bh^T + bias  (A 2-term fp16, B single-rounded fp16)
// CTA tile 256x128, warp tile 64x64 (8 warps = 4m x 2n), BK=32, 3 stages.
// MODE 0: fp32 out; MODE 1: split fp16 out, cols<C_ scaled 0.125 (QKV);
// MODE 2: gelu then split fp16 out.
#define GM_BK    32
#define GM_ROWB  80
#define GM_AOP   (256 * GM_ROWB)              // 20480
#define GM_BOP   (128 * GM_ROWB)              // 10240
#define GM_STAGE (2 * GM_AOP + GM_BOP)        // 51200
#define GM_SMEM  (3 * GM_STAGE)               // 153600

template <int MODE>
__global__ void __launch_bounds__(256, 1) gemm_mma(
    const __half* __restrict__ Ah, const __half* __restrict__ Al,
    const __half* __restrict__ Bh,
    const float* __restrict__ bias, float* __restrict__ Cmat,
    __half* __restrict__ Oh, __half* __restrict__ Ol,
    int N, int K)
{
    extern __shared__ char smem[];
    const uint32_t sb = smem_u32(smem);
    const int tid  = threadIdx.x;
    const int lane = tid & 31;
    const int wid  = tid >> 5;
    const int m0 = blockIdx.y * 256;
    const int n0 = blockIdx.x * 128;
    const int wm = (wid >> 1) * 64;
    const int wn = (wid & 1) * 64;

    const int nch = K / GM_BK;

    auto load_chunk = [&](int c) {
        const int kk = c * GM_BK;
        const uint32_t st = sb + (c % 3) * GM_STAGE;
#pragma unroll
        for (int i = 0; i < 4; i++) {                // A hi+lo: 1024 units each
            int u = tid + i * 256;
            int r = u >> 2, cc = u & 3;
            uint32_t so = r * GM_ROWB + cc * 16;
            size_t ga = (size_t)(m0 + r) * K + kk + cc * 8;
            CP16(st + so,          Ah + ga);
            CP16(st + GM_AOP + so, Al + ga);
        }
#pragma unroll
        for (int i = 0; i < 2; i++) {                // B hi: 512 units
            int u = tid + i * 256;
            int r = u >> 2, cc = u & 3;
            uint32_t so = r * GM_ROWB + cc * 16;
            CP16(st + 2 * GM_AOP + so, Bh + (size_t)(n0 + r) * K + kk + cc * 8);
        }
    };

    float acc[4][8][4];
#pragma unroll
    for (int i = 0; i < 4; i++)
#pragma unroll
        for (int j = 0; j < 8; j++)
#pragma unroll
            for (int t = 0; t < 4; t++) acc[i][j][t] = 0.f;

    load_chunk(0); CP_COMMIT();
    load_chunk(1); CP_COMMIT();

    const int a_row = lane & 15;
    const int a_off = (lane >> 4) * 16;
    const int b_row = (lane & 7) + ((lane >> 4) << 3);
    const int b_off = ((lane >> 3) & 1) * 16;

    for (int k = 0; k < nch; k++) {
        CP_WAIT1();
        __syncthreads();
        if (k + 2 < nch) { load_chunk(k + 2); CP_COMMIT(); }

        const uint32_t stA = sb + (k % 3) * GM_STAGE;
        const uint32_t stB = stA + 2 * GM_AOP;

#pragma unroll
        for (int ks = 0; ks < 2; ks++) {
            uint32_t ah[4][4], al[4][4];
#pragma unroll
            for (int mb = 0; mb < 4; mb++) {
                uint32_t ad = stA + (wm + mb * 16 + a_row) * GM_ROWB + ks * 32 + a_off;
                ldsm4(ah[mb][0], ah[mb][1], ah[mb][2], ah[mb][3], ad);
                ldsm4(al[mb][0], al[mb][1], al[mb][2], al[mb][3], ad + GM_AOP);
            }
#pragma unroll
            for (int nbp = 0; nbp < 4; nbp++) {
                uint32_t bd = stB + (wn + nbp * 16 + b_row) * GM_ROWB + ks * 32 + b_off;
                uint32_t h0, h1, h2, h3;
                ldsm4(h0, h1, h2, h3, bd);
                uint32_t b0h[2] = {h0, h1}, b1h[2] = {h2, h3};
#pragma unroll
                for (int mb = 0; mb < 4; mb++) {
                    MMA16816(acc[mb][2 * nbp],     ah[mb], b0h);
                    MMA16816(acc[mb][2 * nbp],     al[mb], b0h);
                    MMA16816(acc[mb][2 * nbp + 1], ah[mb], b1h);
                    MMA16816(acc[mb][2 * nbp + 1], al[mb], b1h);
                }
            }
        }
    }

    // ---- epilogue ----
    const int gr = lane >> 2;
    const int gc = (lane & 3) * 2;
#pragma unroll
    for (int mb = 0; mb < 4; mb++) {
#pragma unroll
        for (int nb = 0; nb < 8; nb++) {
            int row = m0 + wm + mb * 16 + gr;
            int col = n0 + wn + nb * 8 + gc;
            float b0 = __ldg(&bias[col]), b1 = __ldg(&bias[col + 1]);
            float v0 = acc[mb][nb][0] + b0, v1 = acc[mb][nb][1] + b1;
            float v2 = acc[mb][nb][2] + b0, v3 = acc[mb][nb][3] + b1;
            if (MODE == 0) {
                *(float2*)(Cmat + (size_t)row * N + col)       = make_float2(v0, v1);
                *(float2*)(Cmat + (size_t)(row + 8) * N + col) = make_float2(v2, v3);
            } else {
                if (MODE == 1 && col < C_) { v0 *= 0.125f; v1 *= 0.125f; v2 *= 0.125f; v3 *= 0.125f; }
                if (MODE == 2) {
                    v0 = gelu_exact(v0); v1 = gelu_exact(v1);
                    v2 = gelu_exact(v2); v3 = gelu_exact(v3);
                }
                uint32_t h01, l01, h23, l23;
                split_pack2(v0, v1, h01, l01);
                split_pack2(v2, v3, h23, l23);
                *(uint32_t*)(Oh + (size_t)row * N + col)       = h01;
                *(uint32_t*)(Ol + (size_t)row * N + col)       = l01;
                *(uint32_t*)(Oh + (size_t)(row + 8) * N + col) = h23;
                *(uint32_t*)(Ol + (size_t)(row + 8) * N + col) = l23;
            }
        }
    }
}

// ---------------- tensor-core causal flash attention ------------------------
// 128 queries per CTA (8 warps x 16 rows), 64-key tiles, 3-term fp16 MMAs.
#define AT_ROWB  144
#define AQ_T     (128 * AT_ROWB)             // 18432 per Q operand
#define AK_T     (64 * AT_ROWB)              // 9216 per K/V operand
#define AT_STAGE (4 * AK_T)                  // Kh,Kl,Vh,Vl = 36864
#define AT_SMEM  (2 * AQ_T + 2 * AT_STAGE)   // 110592

__global__ void __launch_bounds__(256, 1) attn_tc(
    const __half* __restrict__ qkvh,
    const __half* __restrict__ qkvl,
    float* __restrict__ y)
{
    extern __shared__ char smem[];
    const uint32_t sb = smem_u32(smem);
    const int tid = threadIdx.x, lane = tid & 31, wid = tid >> 5;
    const int qb = (int)gridDim.x - 1 - (int)blockIdx.x;   // big blocks first
    const int h = blockIdx.y, b = blockIdx.z;
    const int q0 = qb * 128;
    const int wq = wid * 16;
    const int gr = lane >> 2, gc = lane & 3;
    const int RS = 3 * C_;

    const __half* qh = qkvh + (size_t)b * T_ * RS + h * D_;
    const __half* ql = qkvl + (size_t)b * T_ * RS + h * D_;
    const __half* kh = qh + C_;
    const __half* kl = ql + C_;
    const __half* vh = qh + 2 * C_;
    const __half* vl = ql + 2 * C_;

    const uint32_t QH  = sb;
    const uint32_t ST0 = sb + 2 * AQ_T;

    // load Q (hi/lo) tile: 128 rows x 128B each
#pragma unroll
    for (int t = 0; t < 2; t++) {
        const __half* g = t ? ql : qh;
#pragma unroll
        for (int i = 0; i < 4; i++) {
            int u = tid + i * 256;          // 0..1023
            int r = u >> 3, c = u & 7;
            CP16(QH + t * AQ_T + r * AT_ROWB + c * 16, g + (size_t)(q0 + r) * RS + c * 8);
        }
    }

    auto load_tile = [&](int kt, int bufsel) {
        uint32_t st = ST0 + bufsel * AT_STAGE;
#pragma unroll
        for (int t = 0; t < 4; t++) {
            const __half* g = (t == 0 ? kh : t == 1 ? kl : t == 2 ? vh : vl);
#pragma unroll
            for (int i = 0; i < 2; i++) {
                int u = tid + i * 256;      // 0..511
                int r = u >> 3, c = u & 7;
                CP16(st + t * AK_T + r * AT_ROWB + c * 16, g + (size_t)(kt * 64 + r) * RS + c * 8);
            }
        }
    };
    load_tile(0, 0);
    CP_COMMIT();
    CP_WAIT0();
    __syncthreads();

    // Q fragments
    uint32_t qfh[4][4], qfl[4][4];
    const int a_row = lane & 15, a_off = (lane >> 4) * 16;
#pragma unroll
    for (int ks = 0; ks < 4; ks++) {
        uint32_t ad = QH + (wq + a_row) * AT_ROWB + ks * 32 + a_off;
        ldsm4(qfh[ks][0], qfh[ks][1], qfh[ks][2], qfh[ks][3], ad);
        ldsm4(qfl[ks][0], qfl[ks][1], qfl[ks][2], qfl[ks][3], ad + AQ_T);
    }

    float Oacc[8][4];
#pragma unroll
    for (int i = 0; i < 8; i++)
#pragma unroll
        for (int j = 0; j < 4; j++) Oacc[i][j] = 0.f;
    float m0 = -1e30f, m1 = -1e30f, l0 = 0.f, l1 = 0.f;

    const int nt = 2 * qb + 2;
    const int b_row = (lane & 7) + ((lane >> 4) << 3);
    const int b_off = ((lane >> 3) & 1) * 16;
    const int v_row = (lane & 7) + ((lane >> 3) & 1) * 8;
    const int v_off = (lane >> 4) * 16;

    for (int kt = 0; kt < nt; kt++) {
        if (kt + 1 < nt) { load_tile(kt + 1, (kt + 1) & 1); CP_COMMIT(); }
        const uint32_t st = ST0 + (kt & 1) * AT_STAGE;

        // warp-level skip: keys all strictly above this warp's queries
        const bool active = (kt * 64) <= (q0 + wq + 15);
        if (active) {
            // ---- S = Q @ K^T (3-term split) ----
            float sacc[8][4];
#pragma unroll
            for (int i = 0; i < 8; i++)
#pragma unroll
                for (int j = 0; j < 4; j++) sacc[i][j] = 0.f;

#pragma unroll
            for (int nbp = 0; nbp < 4; nbp++) {
#pragma unroll
                for (int ks = 0; ks < 4; ks++) {
                    uint32_t kd = st + (nbp * 16 + b_row) * AT_ROWB + ks * 32 + b_off;
                    uint32_t rh[4], rl[4];
                    ldsm4(rh[0], rh[1], rh[2], rh[3], kd);
                    ldsm4(rl[0], rl[1], rl[2], rl[3], kd + AK_T);
                    uint32_t b0h[2] = {rh[0], rh[1]}, b1h[2] = {rh[2], rh[3]};
                    uint32_t b0l[2] = {rl[0], rl[1]}, b1l[2] = {rl[2], rl[3]};
                    MMA16816(sacc[2 * nbp],     qfh[ks], b0h);
                    MMA16816(sacc[2 * nbp],     qfl[ks], b0h);
                    MMA16816(sacc[2 * nbp],     qfh[ks], b0l);
                    MMA16816(sacc[2 * nbp + 1], qfh[ks], b1h);
                    MMA16816(sacc[2 * nbp + 1], qfl[ks], b1h);
                    MMA16816(sacc[2 * nbp + 1], qfh[ks], b1l);
                }
            }

            // ---- causal mask (only when tile crosses the diagonal) ----
            if (kt * 64 + 63 > q0 + wq) {
                const int qg0 = q0 + wq + gr, qg1 = qg0 + 8;
#pragma unroll
                for (int nb = 0; nb < 8; nb++) {
                    int kg = kt * 64 + nb * 8 + 2 * gc;
                    if (kg     > qg0) sacc[nb][0] = -1e30f;
                    if (kg + 1 > qg0) sacc[nb][1] = -1e30f;
                    if (kg     > qg1) sacc[nb][2] = -1e30f;
                    if (kg + 1 > qg1) sacc[nb][3] = -1e30f;
                }
            }

            // ---- online softmax ----
            float mx0 = m0, mx1 = m1;
#pragma unroll
            for (int nb = 0; nb < 8; nb++) {
                mx0 = fmaxf(mx0, fmaxf(sacc[nb][0], sacc[nb][1]));
                mx1 = fmaxf(mx1, fmaxf(sacc[nb][2], sacc[nb][3]));
            }
            mx0 = fmaxf(mx0, __shfl_xor_sync(0xffffffffu, mx0, 1));
            mx0 = fmaxf(mx0, __shfl_xor_sync(0xffffffffu, mx0, 2));
            mx1 = fmaxf(mx1, __shfl_xor_sync(0xffffffffu, mx1, 1));
            mx1 = fmaxf(mx1, __shfl_xor_sync(0xffffffffu, mx1, 2));
            float al0 = __expf(m0 - mx0), al1 = __expf(m1 - mx1);
            m0 = mx0; m1 = mx1;
            float ls0 = 0.f, ls1 = 0.f;
#pragma unroll
            for (int nb = 0; nb < 8; nb++) {
                sacc[nb][0] = __expf(sacc[nb][0] - mx0); ls0 += sacc[nb][0];
                sacc[nb][1] = __expf(sacc[nb][1] - mx0); ls0 += sacc[nb][1];
                sacc[nb][2] = __expf(sacc[nb][2] - mx1); ls1 += sacc[nb][2];
                sacc[nb][3] = __expf(sacc[nb][3] - mx1); ls1 += sacc[nb][3];
            }
            l0 = l0 * al0 + ls0;
            l1 = l1 * al1 + ls1;
#pragma unroll
            for (int nb = 0; nb < 8; nb++) {
                Oacc[nb][0] *= al0; Oacc[nb][1] *= al0;
                Oacc[nb][2] *= al1; Oacc[nb][3] *= al1;
            }

            // ---- O += P @ V (3-term split) ----
#pragma unroll
            for (int kb = 0; kb < 4; kb++) {
                uint32_t ph[4], pl[4];
                split_pack2(sacc[2 * kb][0],     sacc[2 * kb][1],     ph[0], pl[0]);
                split_pack2(sacc[2 * kb][2],     sacc[2 * kb][3],     ph[1], pl[1]);
                split_pack2(sacc[2 * kb + 1][0], sacc[2 * kb + 1][1], ph[2], pl[2]);
                split_pack2(sacc[2 * kb + 1][2], sacc[2 * kb + 1][3], ph[3], pl[3]);
#pragma unroll
                for (int nbp = 0; nbp < 4; nbp++) {
                    uint32_t vd = st + 2 * AK_T + (kb * 16 + v_row) * AT_ROWB + nbp * 32 + v_off;
                    uint32_t rh[4], rl[4];
                    ldsm4t(rh[0], rh[1], rh[2], rh[3], vd);
                    ldsm4t(rl[0], rl[1], rl[2], rl[3], vd + AK_T);
                    uint32_t v0h[2] = {rh[0], rh[1]}, v1h[2] = {rh[2], rh[3]};
                    uint32_t v0l[2] = {rl[0], rl[1]}, v1l[2] = {rl[2], rl[3]};
                    MMA16816(Oacc[2 * nbp],     ph, v0h);
                    MMA16816(Oacc[2 * nbp],     pl, v0h);
                    MMA16816(Oacc[2 * nbp],     ph, v0l);
                    MMA16816(Oacc[2 * nbp + 1], ph, v1h);
                    MMA16816(Oacc[2 * nbp + 1], pl, v1h);
                    MMA16816(Oacc[2 * nbp + 1], ph, v1l);
                }
            }
        }

        CP_WAIT0();
        __syncthreads();
    }

    // ---- finalize ----
    l0 += __shfl_xor_sync(0xffffffffu, l0, 1);
    l0 += __shfl_xor_sync(0xffffffffu, l0, 2);
    l1 += __shfl_xor_sync(0xffffffffu, l1, 1);
    l1 += __shfl_xor_sync(0xffffffffu, l1, 2);
    const float inv0 = 1.f / l0, inv1 = 1.f / l1;

    float* yb = y + ((size_t)b * T_ + q0 + wq) * C_ + h * D_;
#pragma unroll
    for (int nb = 0; nb < 8; nb++) {
        int col = nb * 8 + 2 * gc;
        *(float2*)(yb + (size_t)gr * C_ + col) =
            make_float2(Oacc[nb][0] * inv0, Oacc[nb][1] * inv0);
        *(float2*)(yb + (size_t)(gr + 8) * C_ + col) =
            make_float2(Oacc[nb][2] * inv1, Oacc[nb][3] * inv1);
    }
}

// ---------------- residual add + LayerNorm (+ optional split) --------------
template <bool SPLIT>
__global__ void __launch_bounds__(256) add_ln_kernel(
    const float* __restrict__ a, const float* __restrict__ bres,
    const float* __restrict__ g, const float* __restrict__ beta,
    float* __restrict__ out, __half* __restrict__ Oh,
    __half* __restrict__ Ol)
{
    const int row = blockIdx.x;
    const int tid = threadIdx.x;

    const float4 av = ((const float4*)(a    + (size_t)row * C_))[tid];
    const float4 bv = ((const float4*)(bres + (size_t)row * C_))[tid];
    float4 v = make_float4(av.x + bv.x, av.y + bv.y, av.z + bv.z, av.w + bv.w);

    float s  = v.x + v.y + v.z + v.w;
    float sq = v.x * v.x + v.y * v.y + v.z * v.z + v.w * v.w;
#pragma unroll
    for (int off = 16; off; off >>= 1) {
        s  += __shfl_xor_sync(0xffffffffu, s,  off);
        sq += __shfl_xor_sync(0xffffffffu, sq, off);
    }
    __shared__ float ws[8], wsq[8];
    if ((tid & 31) == 0) { ws[tid >> 5] = s; wsq[tid >> 5] = sq; }
    __syncthreads();
    float tot = 0.f, totq = 0.f;
#pragma unroll
    for (int i = 0; i < 8; i++) { tot += ws[i]; totq += wsq[i]; }

    const float mu   = tot * (1.0f / C_);
    const float var  = totq * (1.0f / C_) - mu * mu;
    const float rstd = rsqrtf(var + LN_EPS);

    const float4 gv = ((const float4*)g)[tid];
    const float4 be = ((const float4*)beta)[tid];
    float4 o;
    o.x = (v.x - mu) * rstd * gv.x + be.x;
    o.y = (v.y - mu) * rstd * gv.y + be.y;
    o.z = (v.z - mu) * rstd * gv.z + be.z;
    o.w = (v.w - mu) * rstd * gv.w + be.w;
    ((float4*)(out + (size_t)row * C_))[tid] = o;
    if (SPLIT) {
        uint32_t h0, l0v, h1, l1v;
        split_pack2(o.x, o.y, h0, l0v);
        split_pack2(o.z, o.w, h1, l1v);
        uint32_t* oh = (uint32_t*)(Oh + (size_t)row * C_);
        uint32_t* ol = (uint32_t*)(Ol + (size_t)row * C_);
        oh[2 * tid] = h0; oh[2 * tid + 1] = h1;
        ol[2 * tid] = l0v; ol[2 * tid + 1] = l1v;
    }
}

// ---------------- launcher --------------------------------------------------
extern "C" void kernel_launch(void* const* d_in, const int* in_sizes, int n_in,
                              void* d_out, int out_size)
{
    const float* x     = (const float*)d_in[0];
    const float* w_qkv = (const float*)d_in[1];
    const float* b_qkv = (const float*)d_in[2];
    const float* ln1_g = (const float*)d_in[3];
    const float* ln1_b = (const float*)d_in[4];
    const float* w_fc1 = (const float*)d_in[5];
    const float* b_fc1 = (const float*)d_in[6];
    const float* w_fc2 = (const float*)d_in[7];
    const float* b_fc2 = (const float*)d_in[8];
    const float* ln2_g = (const float*)d_in[9];
    const float* ln2_b = (const float*)d_in[10];
    float* out = (float*)d_out;

    float *att, *x1, *mlp;
    __half *qkvh, *qkvl, *ah, *al, *ah2, *al2, *bh;
    cudaGetSymbolAddress((void**)&att,  g_att);
    cudaGetSymbolAddress((void**)&x1,   g_x1);
    cudaGetSymbolAddress((void**)&mlp,  g_mlp);
    cudaGetSymbolAddress((void**)&qkvh, g_qkvh);
    cudaGetSymbolAddress((void**)&qkvl, g_qkvl);
    cudaGetSymbolAddress((void**)&ah,   g_ah);
    cudaGetSymbolAddress((void**)&al,   g_al);
    cudaGetSymbolAddress((void**)&ah2,  g_ah2);
    cudaGetSymbolAddress((void**)&al2,  g_al2);
    cudaGetSymbolAddress((void**)&bh,   g_bh);

    cudaFuncSetAttribute(gemm_mma<0>, cudaFuncAttributeMaxDynamicSharedMemorySize, GM_SMEM);
    cudaFuncSetAttribute(gemm_mma<1>, cudaFuncAttributeMaxDynamicSharedMemorySize, GM_SMEM);
    cudaFuncSetAttribute(gemm_mma<2>, cudaFuncAttributeMaxDynamicSharedMemorySize, GM_SMEM);
    cudaFuncSetAttribute(attn_tc, cudaFuncAttributeMaxDynamicSharedMemorySize, AT_SMEM);

    // ---- QKV = x @ w_qkv + b  -> split fp16 (Q scaled 1/8) ----
    split_act<<<(M_ * C_ / 4 + 255) / 256, 256>>>(x, ah, al, (size_t)M_ * C_ / 4);
    round_w_t<<<dim3(3 * C_ / 32, C_ / 32), dim3(32, 8)>>>(w_qkv, bh, C_, 3 * C_);
    gemm_mma<1><<<dim3(3 * C_ / 128, M_ / 256), 256, GM_SMEM>>>(
        ah, al, bh, b_qkv, nullptr, qkvh, qkvl, 3 * C_, C_);

    // ---- attention (tensor core, 128 q / CTA) ----
    attn_tc<<<dim3(T_ / 128, H_, B_), 256, AT_SMEM>>>(qkvh, qkvl, att);

    // ---- x1 = LN1(x + att), fused split for FC1 A ----
    add_ln_kernel<true><<<M_, 256>>>(x, att, ln1_g, ln1_b, x1, ah, al);

    // ---- h = gelu(x1 @ w_fc1 + b) -> split fp16 ----
    round_w_t<<<dim3(4 * C_ / 32, C_ / 32), dim3(32, 8)>>>(w_fc1, bh, C_, 4 * C_);
    gemm_mma<2><<<dim3(4 * C_ / 128, M_ / 256), 256, GM_SMEM>>>(
        ah, al, bh, b_fc1, nullptr, ah2, al2, 4 * C_, C_);

    // ---- mlp = h @ w_fc2 + b (fp32) ----
    round_w_t<<<dim3(C_ / 32, 4 * C_ / 32), dim3(32, 8)>>>(w_fc2, bh, 4 * C_, C_);
    gemm_mma<0><<<dim3(C_ / 128, M_ / 256), 256, GM_SMEM>>>(
        ah2, al2, bh, b_fc2, mlp, nullptr, nullptr, C_, 4 * C_);

    // ---- out = LN2(x1 + mlp) ----
    add_ln_kernel<false><<<M_, 256>>>(x1, mlp, ln2_g, ln2_b, out, nullptr, nullptr);
}